// round 6
// baseline (speedup 1.0000x reference)
#include <cuda_runtime.h>
#include <cuda_bf16.h>
#include <cuda_fp16.h>
#include <cstdint>

#define H 64
#define MAXN 100000
#define MAXE 1600000
#define MAXL 8

typedef unsigned long long u64;

// ---------------- device scratch (static: no dynamic allocation allowed) ----
__device__ float         g_h[(size_t)MAXN * H];
__device__ float         g_A[(size_t)MAXN * H];
__device__ unsigned int  g_aggr[(size_t)MAXN * H];
__device__ int           g_cnt[MAXN];
__device__ int           g_cursor[MAXN];
__device__ int           g_perm[MAXE];
__device__ __half        g_Bh[MAXL * 64 * 72];  // per-layer W2^T fp16, [n][72] rows

// order-preserving float<->uint encoding for atomic min
__device__ __forceinline__ unsigned fenc(float f) {
    unsigned u = __float_as_uint(f);
    return (u & 0x80000000u) ? ~u : (u | 0x80000000u);
}
__device__ __forceinline__ float fdec(unsigned u) {
    return (u & 0x80000000u) ? __uint_as_float(u & 0x7FFFFFFFu)
                             : __uint_as_float(~u);
}

// -------- packed f32x2 helpers (node GEMMs) --------------------------------
__device__ __forceinline__ u64 pk_dup(float x) {
    u64 r;
    asm("mov.b64 %0, {%1,%1};" : "=l"(r) : "f"(x));
    return r;
}
__device__ __forceinline__ void fma2(u64& d, u64 a, u64 b) {
    asm("fma.rn.f32x2 %0, %1, %2, %3;" : "=l"(d) : "l"(a), "l"(b), "l"(d));
}
__device__ __forceinline__ void unpk(float& lo, float& hi, u64 v) {
    asm("mov.b64 {%0,%1}, %2;" : "=f"(lo), "=f"(hi) : "l"(v));
}

// -------- warp-mma plumbing (plain sm_80+ PTX) -----------------------------
__device__ __forceinline__ uint32_t smem_u32(const void* p) {
    uint32_t a;
    asm("{ .reg .u64 t; cvta.to.shared.u64 t, %1; cvt.u32.u64 %0, t; }"
        : "=r"(a) : "l"(p));
    return a;
}
__device__ __forceinline__ void ldsm4(uint32_t (&r)[4], uint32_t addr) {
    asm volatile("ldmatrix.sync.aligned.m8n8.x4.shared.b16 {%0,%1,%2,%3}, [%4];"
                 : "=r"(r[0]), "=r"(r[1]), "=r"(r[2]), "=r"(r[3]) : "r"(addr));
}
__device__ __forceinline__ void mma16816h(float (&d)[4], const uint32_t (&a)[4],
                                          uint32_t b0, uint32_t b1) {
    asm volatile(
        "mma.sync.aligned.m16n8k16.row.col.f32.f16.f16.f32 "
        "{%0,%1,%2,%3}, {%4,%5,%6,%7}, {%8,%9}, {%0,%1,%2,%3};"
        : "+f"(d[0]), "+f"(d[1]), "+f"(d[2]), "+f"(d[3])
        : "r"(a[0]), "r"(a[1]), "r"(a[2]), "r"(a[3]), "r"(b0), "r"(b1));
}
// pack f16(even)|f16(odd)<<16
__device__ __forceinline__ uint32_t cvt2h(float odd, float even) {
    uint32_t d;
    asm("cvt.rn.f16x2.f32 %0, %1, %2;" : "=r"(d) : "f"(odd), "f"(even));
    return d;
}

// ---------------- trivial elementwise kernels ------------------------------
__global__ void embed_kernel(const float* __restrict__ x,
                             const float* __restrict__ w,
                             const float* __restrict__ b,
                             float* __restrict__ h, int* __restrict__ cnt,
                             int n) {
    int i = blockIdx.x * blockDim.x + threadIdx.x;
    if (i < n) cnt[i] = 0;
    if (i < n * H) {
        int node = i >> 6, j = i & 63;
        h[i] = fmaf(x[node], w[j], b[j]);
    }
}

__global__ void count_kernel(const int* __restrict__ dst, int* cnt, int e) {
    int i = blockIdx.x * blockDim.x + threadIdx.x;
    if (i < e) atomicAdd(&cnt[dst[i]], 1);
}

// prefix scan of cnt + precompute per-layer fp16 B = W2^T (stride 72)
__global__ void scan_prep_kernel(const int* __restrict__ cnt,
                                 int* __restrict__ cursor, int n,
                                 const float* __restrict__ mw2, int L) {
    int tid = threadIdx.x;
    int total = L * H * H;
    for (int i = tid; i < total; i += 1024) {
        int l = i >> 12, rem = i & 4095;
        int nn = rem >> 6, k = rem & 63;
        float w = mw2[(size_t)l * 4096 + k * 64 + nn];
        g_Bh[(size_t)l * (64 * 72) + nn * 72 + k] = __float2half_rn(w);
    }
    __shared__ int s[1024];
    int chunk = (n + 1023) >> 10;
    int lo = tid * chunk;
    int hi = min(lo + chunk, n);
    int sum = 0;
    for (int i = lo; i < hi; i++) sum += cnt[i];
    s[tid] = sum;
    __syncthreads();
    for (int off = 1; off < 1024; off <<= 1) {
        int v = (tid >= off) ? s[tid - off] : 0;
        __syncthreads();
        s[tid] += v;
        __syncthreads();
    }
    int run = s[tid] - sum;
    for (int i = lo; i < hi; i++) { cursor[i] = run; run += cnt[i]; }
}

// scatter (build perm) + init aggr to encoded +inf
__global__ void scatter_kernel(const int* __restrict__ dst, int* cursor,
                               int* perm, unsigned* __restrict__ aggr,
                               int e, int nH4) {
    int i = blockIdx.x * blockDim.x + threadIdx.x;
    if (i < e) {
        int p = atomicAdd(&cursor[dst[i]], 1);
        perm[p] = i;
    }
    uint4 f = make_uint4(~0u, ~0u, ~0u, ~0u);
    for (int j = i; j < nH4; j += gridDim.x * blockDim.x)
        ((uint4*)aggr)[j] = f;
}

__global__ void fc_kernel(const float* __restrict__ h,
                          const float* __restrict__ fcw,
                          const float* __restrict__ fcb,
                          float* __restrict__ out, int n) {
    int i = blockIdx.x * blockDim.x + threadIdx.x;
    if (i >= n) return;
    const float4* h4 = (const float4*)(h + (size_t)i * H);
    const float4* w4 = (const float4*)fcw;
    float s = 0.f;
#pragma unroll
    for (int q = 0; q < 16; q++) {
        float4 a = h4[q], w = w4[q];
        s += a.x * w.x + a.y * w.y + a.z * w.z + a.w * w.w;
    }
    out[i] = s + fcb[0];
}

// -------- node GEMM (fp32 f32x2 path; DECODE fuses aggr finalize) ----------
template <int K>
__device__ __forceinline__ void gemm_body(const float* Xs, const float* Ws,
                                          int ty, int tx, u64 acc2[8][4]) {
    const float4* Xs4 = (const float4*)Xs;
#pragma unroll 4
    for (int k = 0; k < K; k++) {
        float4 a0 = Xs4[k * 32 + ty * 2];
        float4 a1 = Xs4[k * 32 + ty * 2 + 1];
        const ulonglong2* Wp = (const ulonglong2*)(Ws + k * 64 + tx * 8);
        ulonglong2 w01 = Wp[0];
        ulonglong2 w23 = Wp[1];
        u64 aa[8] = {pk_dup(a0.x), pk_dup(a0.y), pk_dup(a0.z), pk_dup(a0.w),
                     pk_dup(a1.x), pk_dup(a1.y), pk_dup(a1.z), pk_dup(a1.w)};
#pragma unroll
        for (int r = 0; r < 8; r++) {
            fma2(acc2[r][0], aa[r], w01.x);
            fma2(acc2[r][1], aa[r], w01.y);
            fma2(acc2[r][2], aa[r], w23.x);
            fma2(acc2[r][3], aa[r], w23.y);
        }
    }
}

template <int K, bool RELU, bool DECODE>
__global__ void __launch_bounds__(128)
node_gemm(const float* __restrict__ X1, const void* __restrict__ X2p,
          const float* __restrict__ W, const float* __restrict__ bias,
          float* __restrict__ C, int Nn,
          const float* __restrict__ b2g, unsigned* __restrict__ aggrw) {
    extern __shared__ float sm[];
    float* Ws = sm;
    float* Xs = sm + K * 64;
    float* b2s = sm + K * 64 + K * 128;   // 64 floats (DECODE only)
    int tid = threadIdx.x;
    int n0 = blockIdx.x * 128;
    {
        const float4* W4 = (const float4*)W;
        float4* Ws4 = (float4*)Ws;
#pragma unroll
        for (int i = 0; i < K / 8; i++) Ws4[tid + i * 128] = W4[tid + i * 128];
    }
    int n = min(n0 + tid, Nn - 1);
    {
        const float4* X14 = (const float4*)(X1 + (size_t)n * H);
#pragma unroll
        for (int q = 0; q < 16; q++) {
            float4 v = X14[q];
            Xs[(4 * q + 0) * 128 + tid] = v.x;
            Xs[(4 * q + 1) * 128 + tid] = v.y;
            Xs[(4 * q + 2) * 128 + tid] = v.z;
            Xs[(4 * q + 3) * 128 + tid] = v.w;
        }
    }
    if (DECODE) {
        if (tid < 64) b2s[tid] = b2g[tid];
        __syncthreads();
    }
    if (K == 128) {
        if (DECODE) {
            const uint4* X24 = (const uint4*)((const unsigned*)X2p +
                                              (size_t)n * H);
#pragma unroll
            for (int q = 0; q < 16; q++) {
                uint4 u = X24[q];
                float4 v;
                v.x = (u.x >= 0xFF800000u) ? 0.f : (fdec(u.x) + b2s[4 * q + 0]);
                v.y = (u.y >= 0xFF800000u) ? 0.f : (fdec(u.y) + b2s[4 * q + 1]);
                v.z = (u.z >= 0xFF800000u) ? 0.f : (fdec(u.z) + b2s[4 * q + 2]);
                v.w = (u.w >= 0xFF800000u) ? 0.f : (fdec(u.w) + b2s[4 * q + 3]);
                Xs[(64 + 4 * q + 0) * 128 + tid] = v.x;
                Xs[(64 + 4 * q + 1) * 128 + tid] = v.y;
                Xs[(64 + 4 * q + 2) * 128 + tid] = v.z;
                Xs[(64 + 4 * q + 3) * 128 + tid] = v.w;
            }
            // re-poison aggr for next layer (owner thread only; safe at tail)
            if (n0 + tid < Nn) {
                uint4 p = make_uint4(~0u, ~0u, ~0u, ~0u);
                uint4* A4 = (uint4*)(aggrw + (size_t)n * H);
#pragma unroll
                for (int q = 0; q < 16; q++) A4[q] = p;
            }
        } else {
            const float4* X24 = (const float4*)((const float*)X2p +
                                                (size_t)n * H);
#pragma unroll
            for (int q = 0; q < 16; q++) {
                float4 v = X24[q];
                Xs[(64 + 4 * q + 0) * 128 + tid] = v.x;
                Xs[(64 + 4 * q + 1) * 128 + tid] = v.y;
                Xs[(64 + 4 * q + 2) * 128 + tid] = v.z;
                Xs[(64 + 4 * q + 3) * 128 + tid] = v.w;
            }
        }
    }
    __syncthreads();
    int ty = tid >> 3, tx = tid & 7;
    u64 acc2[8][4];
#pragma unroll
    for (int r = 0; r < 8; r++)
#pragma unroll
        for (int c = 0; c < 4; c++) acc2[r][c] = 0ull;
    gemm_body<K>(Xs, Ws, ty, tx, acc2);
    float bb[8];
#pragma unroll
    for (int c = 0; c < 8; c++) bb[c] = bias[tx * 8 + c];
#pragma unroll
    for (int r = 0; r < 8; r++) {
        int nr = n0 + ty * 8 + r;
        if (nr < Nn) {
            float o[8];
            unpk(o[0], o[1], acc2[r][0]);
            unpk(o[2], o[3], acc2[r][1]);
            unpk(o[4], o[5], acc2[r][2]);
            unpk(o[6], o[7], acc2[r][3]);
            float4 o0, o1;
            o0.x = o[0] + bb[0]; o0.y = o[1] + bb[1];
            o0.z = o[2] + bb[2]; o0.w = o[3] + bb[3];
            o1.x = o[4] + bb[4]; o1.y = o[5] + bb[5];
            o1.z = o[6] + bb[6]; o1.w = o[7] + bb[7];
            if (RELU) {
                o0.x = fmaxf(o0.x, 0.f); o0.y = fmaxf(o0.y, 0.f);
                o0.z = fmaxf(o0.z, 0.f); o0.w = fmaxf(o0.w, 0.f);
                o1.x = fmaxf(o1.x, 0.f); o1.y = fmaxf(o1.y, 0.f);
                o1.z = fmaxf(o1.z, 0.f); o1.w = fmaxf(o1.w, 0.f);
            }
            float4* C4 = (float4*)(C + (size_t)nr * H);
            C4[tx * 2] = o0;
            C4[tx * 2 + 1] = o1;
        }
    }
}

// ---------------- HMMA edge kernel (persistent, single-term fp16) ----------
// Per 128-edge tile: T = relu(A[src]+ev*we) -> fp16 rows (stride 72);
// D[128,64] = T@B^T via mma.sync m16n8k16 (fp32 acc; rounding ~2^-11/layer,
// damped ~40x by min-aggregation + contractive MLPs -> final ~3e-5);
// D staged to XOR-swizzled SMEM -> segmented min by sorted dst -> atomicMin.
#define TH_OFF   0            // 128 x 72 f16 = 18432 B (Ds overlay: 32768 B)
#define BH_OFF   32768        // 64 x 72 f16 = 9216 B
#define WES_OFF  41984        // 64 f32
#define DST_OFF  42240        // 128 int
#define SMEM_EDGE 42752

__global__ void __launch_bounds__(128, 5)
edge_mma_kernel(const float* __restrict__ Ag, const int* __restrict__ src,
                const int* __restrict__ dstp, const float* __restrict__ ea,
                const int* __restrict__ perm, const float* __restrict__ weg,
                const __half* __restrict__ Bh_g,
                unsigned* __restrict__ aggr, int E, int ntiles) {
    extern __shared__ char smc[];
    uint32_t sb = smem_u32(smc);
    int tid = threadIdx.x;
    int lane = tid & 31;
    int wid = tid >> 5;

    // one-time: copy B (576 uint4) + we into smem
    {
        const uint4* s4 = (const uint4*)Bh_g;
        uint4* d4 = (uint4*)(smc + BH_OFF);
        for (int i = tid; i < 576; i += 128) d4[i] = s4[i];
        if (tid < 64) ((float*)(smc + WES_OFF))[tid] = weg[tid];
    }
    __syncthreads();

    const float* wes = (const float*)(smc + WES_OFF);
    int* dstL = (int*)(smc + DST_OFF);
    float* Ds = (float*)smc;   // overlays T after mma reads complete

    int m0 = wid * 32;
    // ldmatrix lane-address components
    uint32_t aRow = (lane & 7) + 8u * ((lane >> 3) & 1);
    uint32_t aKoff = 16u * (lane >> 4);
    uint32_t bBase = 144u * (8u * ((lane >> 4) & 1) + (lane & 7)) +
                     16u * ((lane >> 3) & 1);

    for (int tile = blockIdx.x; tile < ntiles; tile += gridDim.x) {
        // ---- gather + relu + fp16 convert -> T rows (144B stride) ----
        {
            int slot = tile * 128 + tid;
            int eidx = perm[min(slot, E - 1)];
            int s = src[eidx];
            float ev = ea[eidx];
            dstL[tid] = (slot < E) ? dstp[eidx] : -1;
            const float4* A4 = (const float4*)(Ag + (size_t)s * H);
            char* thRow = smc + TH_OFF + tid * 144;
#pragma unroll
            for (int q = 0; q < 8; q++) {
                float4 a0 = A4[2 * q], a1 = A4[2 * q + 1];
                float v[8];
                v[0] = fmaxf(fmaf(ev, wes[q * 8 + 0], a0.x), 0.f);
                v[1] = fmaxf(fmaf(ev, wes[q * 8 + 1], a0.y), 0.f);
                v[2] = fmaxf(fmaf(ev, wes[q * 8 + 2], a0.z), 0.f);
                v[3] = fmaxf(fmaf(ev, wes[q * 8 + 3], a0.w), 0.f);
                v[4] = fmaxf(fmaf(ev, wes[q * 8 + 4], a1.x), 0.f);
                v[5] = fmaxf(fmaf(ev, wes[q * 8 + 5], a1.y), 0.f);
                v[6] = fmaxf(fmaf(ev, wes[q * 8 + 6], a1.z), 0.f);
                v[7] = fmaxf(fmaf(ev, wes[q * 8 + 7], a1.w), 0.f);
                uint4 hp;
                hp.x = cvt2h(v[1], v[0]);
                hp.y = cvt2h(v[3], v[2]);
                hp.z = cvt2h(v[5], v[4]);
                hp.w = cvt2h(v[7], v[6]);
                *(uint4*)(thRow + q * 16) = hp;
            }
        }
        __syncthreads();

        // ---- warp MMA: rows m0..m0+31, 4 k-steps, single fp16 term ----
        float acc[2][8][4];
#pragma unroll
        for (int mt = 0; mt < 2; mt++)
#pragma unroll
            for (int nt = 0; nt < 8; nt++)
#pragma unroll
                for (int c = 0; c < 4; c++) acc[mt][nt][c] = 0.f;

#pragma unroll
        for (int ks = 0; ks < 4; ks++) {
            uint32_t ah0[4], ah1[4];
            ldsm4(ah0, sb + TH_OFF + 144u * (m0 + aRow) + 32u * ks + aKoff);
            ldsm4(ah1, sb + TH_OFF + 144u * (m0 + 16 + aRow) + 32u * ks + aKoff);
#pragma unroll
            for (int ntp = 0; ntp < 4; ntp++) {
                uint32_t b4[4];
                ldsm4(b4, sb + BH_OFF + bBase + 2304u * ntp + 32u * ks);
                mma16816h(acc[0][2 * ntp], ah0, b4[0], b4[1]);
                mma16816h(acc[1][2 * ntp], ah1, b4[0], b4[1]);
                mma16816h(acc[0][2 * ntp + 1], ah0, b4[2], b4[3]);
                mma16816h(acc[1][2 * ntp + 1], ah1, b4[2], b4[3]);
            }
        }
        __syncthreads();   // T reads done before Ds overlay writes

        // ---- stage D to swizzled SMEM: float4 slot = e*16 + (c4^(e&15)) ----
#pragma unroll
        for (int mt = 0; mt < 2; mt++) {
            int eb = m0 + mt * 16 + (lane >> 2);
            int h2i = lane & 1;
            int c4b = (lane & 3) >> 1;
#pragma unroll
            for (int nt = 0; nt < 8; nt++) {
                int c4 = nt * 2 + c4b;
                float2 v0 = make_float2(acc[mt][nt][0], acc[mt][nt][1]);
                float2 v1 = make_float2(acc[mt][nt][2], acc[mt][nt][3]);
                int e0 = eb, e1 = eb + 8;
                ((float2*)(Ds + (e0 * 16 + (c4 ^ (e0 & 15))) * 4))[h2i] = v0;
                ((float2*)(Ds + (e1 * 16 + (c4 ^ (e1 & 15))) * 4))[h2i] = v1;
            }
        }
        __syncthreads();

        // ---- epilogue: segmented min over 8 sorted edges, atomicMin ----
        {
            const float4* Ds4 = (const float4*)Ds;
            int ty = tid >> 3, tx = tid & 7;
            int cur = -2;
            float4 mA, mB;
#pragma unroll
            for (int r = 0; r < 8; r++) {
                int e = ty * 8 + r;
                int d = dstL[e];
                float4 a = Ds4[e * 16 + (tx ^ (e & 15))];
                float4 b = Ds4[e * 16 + ((8 + tx) ^ (e & 15))];
                if (r == 0 || d != cur) {
                    if (r > 0 && cur >= 0) {
                        unsigned* p0 = aggr + (size_t)cur * H + tx * 4;
                        atomicMin(p0 + 0, fenc(mA.x));
                        atomicMin(p0 + 1, fenc(mA.y));
                        atomicMin(p0 + 2, fenc(mA.z));
                        atomicMin(p0 + 3, fenc(mA.w));
                        unsigned* p1 = p0 + 32;
                        atomicMin(p1 + 0, fenc(mB.x));
                        atomicMin(p1 + 1, fenc(mB.y));
                        atomicMin(p1 + 2, fenc(mB.z));
                        atomicMin(p1 + 3, fenc(mB.w));
                    }
                    cur = d;
                    mA = a; mB = b;
                } else {
                    mA.x = fminf(mA.x, a.x); mA.y = fminf(mA.y, a.y);
                    mA.z = fminf(mA.z, a.z); mA.w = fminf(mA.w, a.w);
                    mB.x = fminf(mB.x, b.x); mB.y = fminf(mB.y, b.y);
                    mB.z = fminf(mB.z, b.z); mB.w = fminf(mB.w, b.w);
                }
            }
            if (cur >= 0) {
                unsigned* p0 = aggr + (size_t)cur * H + tx * 4;
                atomicMin(p0 + 0, fenc(mA.x));
                atomicMin(p0 + 1, fenc(mA.y));
                atomicMin(p0 + 2, fenc(mA.z));
                atomicMin(p0 + 3, fenc(mA.w));
                unsigned* p1 = p0 + 32;
                atomicMin(p1 + 0, fenc(mB.x));
                atomicMin(p1 + 1, fenc(mB.y));
                atomicMin(p1 + 2, fenc(mB.z));
                atomicMin(p1 + 3, fenc(mB.w));
            }
        }
        __syncthreads();   // Ds/dstL dead before next tile's writes
    }
}

// ---------------- host launch ----------------------------------------------
extern "C" void kernel_launch(void* const* d_in, const int* in_sizes, int n_in,
                              void* d_out, int out_size) {
    const float* x    = (const float*)d_in[0];
    const int*   ei   = (const int*)d_in[1];
    const float* ea   = (const float*)d_in[2];
    const float* embw = (const float*)d_in[3];
    const float* embb = (const float*)d_in[4];
    const float* mw1  = (const float*)d_in[5];
    const float* mb1  = (const float*)d_in[6];
    const float* mw2  = (const float*)d_in[7];
    const float* mb2  = (const float*)d_in[8];
    const float* uw1  = (const float*)d_in[9];
    const float* ub1  = (const float*)d_in[10];
    const float* uw2  = (const float*)d_in[11];
    const float* ub2  = (const float*)d_in[12];
    const float* fcw  = (const float*)d_in[13];
    const float* fcb  = (const float*)d_in[14];
    float* out = (float*)d_out;

    int N = in_sizes[0];
    int E = in_sizes[2];
    int L = in_sizes[6] / H;
    const int* src = ei;
    const int* dstp = ei + E;

    float* hbuf; float* Abuf; unsigned* aggr;
    int* cnt; int* cursor; int* perm;
    __half* Bh;
    cudaGetSymbolAddress((void**)&hbuf, g_h);
    cudaGetSymbolAddress((void**)&Abuf, g_A);
    cudaGetSymbolAddress((void**)&aggr, g_aggr);
    cudaGetSymbolAddress((void**)&cnt, g_cnt);
    cudaGetSymbolAddress((void**)&cursor, g_cursor);
    cudaGetSymbolAddress((void**)&perm, g_perm);
    cudaGetSymbolAddress((void**)&Bh, g_Bh);

    const size_t sm64  = (64 * 64 + 64 * 128) * 4;
    const size_t sm128 = (128 * 64 + 128 * 128 + 64) * 4;
    cudaFuncSetAttribute(edge_mma_kernel,
                         cudaFuncAttributeMaxDynamicSharedMemorySize, SMEM_EDGE);
    cudaFuncSetAttribute((node_gemm<64, false, false>),
                         cudaFuncAttributeMaxDynamicSharedMemorySize, (int)sm64);
    cudaFuncSetAttribute((node_gemm<128, true, true>),
                         cudaFuncAttributeMaxDynamicSharedMemorySize, (int)sm128);

    int ntiles = (E + 127) / 128;
    int edgeGrid = 148 * 5;
    if (edgeGrid > ntiles) edgeGrid = ntiles;
    int nodeBlocks = (N + 127) / 128;

    // embedding (+ zero cnt)
    embed_kernel<<<(N * H + 255) / 256, 256>>>(x, embw, embb, hbuf, cnt, N);
    // counting sort by dst (+ B fp16 prep, + aggr poison)
    count_kernel<<<(E + 255) / 256, 256>>>(dstp, cnt, E);
    scan_prep_kernel<<<1, 1024>>>(cnt, cursor, N, mw2, L);
    scatter_kernel<<<(E + 255) / 256, 256>>>(dstp, cursor, perm, aggr, E,
                                             N * H / 4);

    for (int l = 0; l < L; l++) {
        const float* w1 = mw1 + (size_t)l * (H + 1) * H;   // [65,64]
        // A = h @ W1[:64] + b1  (per-node hoist of per-edge msg layer 1)
        node_gemm<64, false, false><<<nodeBlocks, 128, sm64>>>(
            hbuf, nullptr, w1, mb1 + (size_t)l * H, Abuf, N, nullptr, nullptr);
        // tensor-pipe edge message + scatter-min
        edge_mma_kernel<<<edgeGrid, 128, SMEM_EDGE>>>(
            Abuf, src, dstp, ea, perm, w1 + (size_t)H * H,
            Bh + (size_t)l * (64 * 72), aggr, E, ntiles);
        // update MLP layer 1 (fused aggr decode + b2 + re-poison)
        node_gemm<128, true, true><<<nodeBlocks, 128, sm128>>>(
            hbuf, aggr, uw1 + (size_t)l * 2 * H * H, ub1 + (size_t)l * H,
            Abuf, N, mb2 + (size_t)l * H, aggr);
        // update MLP layer 2
        node_gemm<64, false, false><<<nodeBlocks, 128, sm64>>>(
            Abuf, nullptr, uw2 + (size_t)l * H * H, ub2 + (size_t)l * H,
            hbuf, N, nullptr, nullptr);
    }

    fc_kernel<<<(N + 255) / 256, 256>>>(hbuf, fcw, fcb, out, N);
}

// round 7
// speedup vs baseline: 1.1862x; 1.1862x over previous
#include <cuda_runtime.h>
#include <cuda_bf16.h>
#include <cuda_fp16.h>
#include <cstdint>

#define H 64
#define MAXN 100000
#define MAXE 1600000
#define MAXL 8

typedef unsigned long long u64;

// ---------------- device scratch (static: no dynamic allocation allowed) ----
__device__ float         g_h[(size_t)MAXN * H];
__device__ float         g_A[(size_t)MAXN * H];
__device__ unsigned int  g_aggr[(size_t)MAXN * H];
__device__ int           g_cnt[MAXN];
__device__ int           g_cursor[MAXN];
__device__ int           g_perm[MAXE];
__device__ __half        g_Bh[MAXL * 64 * 72];  // per-layer W2^T fp16, [n][72] rows

// order-preserving float<->uint encoding for atomic min
__device__ __forceinline__ unsigned fenc(float f) {
    unsigned u = __float_as_uint(f);
    return (u & 0x80000000u) ? ~u : (u | 0x80000000u);
}
__device__ __forceinline__ float fdec(unsigned u) {
    return (u & 0x80000000u) ? __uint_as_float(u & 0x7FFFFFFFu)
                             : __uint_as_float(~u);
}

// -------- packed f32x2 helpers (node GEMMs) --------------------------------
__device__ __forceinline__ u64 pk_dup(float x) {
    u64 r;
    asm("mov.b64 %0, {%1,%1};" : "=l"(r) : "f"(x));
    return r;
}
__device__ __forceinline__ void fma2(u64& d, u64 a, u64 b) {
    asm("fma.rn.f32x2 %0, %1, %2, %3;" : "=l"(d) : "l"(a), "l"(b), "l"(d));
}
__device__ __forceinline__ void unpk(float& lo, float& hi, u64 v) {
    asm("mov.b64 {%0,%1}, %2;" : "=f"(lo), "=f"(hi) : "l"(v));
}

// -------- warp-mma plumbing (plain sm_80+ PTX) -----------------------------
__device__ __forceinline__ uint32_t smem_u32(const void* p) {
    uint32_t a;
    asm("{ .reg .u64 t; cvta.to.shared.u64 t, %1; cvt.u32.u64 %0, t; }"
        : "=r"(a) : "l"(p));
    return a;
}
__device__ __forceinline__ void ldsm4(uint32_t (&r)[4], uint32_t addr) {
    asm volatile("ldmatrix.sync.aligned.m8n8.x4.shared.b16 {%0,%1,%2,%3}, [%4];"
                 : "=r"(r[0]), "=r"(r[1]), "=r"(r[2]), "=r"(r[3]) : "r"(addr));
}
__device__ __forceinline__ void mma16816h(float (&d)[4], const uint32_t (&a)[4],
                                          uint32_t b0, uint32_t b1) {
    asm volatile(
        "mma.sync.aligned.m16n8k16.row.col.f32.f16.f16.f32 "
        "{%0,%1,%2,%3}, {%4,%5,%6,%7}, {%8,%9}, {%0,%1,%2,%3};"
        : "+f"(d[0]), "+f"(d[1]), "+f"(d[2]), "+f"(d[3])
        : "r"(a[0]), "r"(a[1]), "r"(a[2]), "r"(a[3]), "r"(b0), "r"(b1));
}
// pack f16(even)|f16(odd)<<16
__device__ __forceinline__ uint32_t cvt2h(float odd, float even) {
    uint32_t d;
    asm("cvt.rn.f16x2.f32 %0, %1, %2;" : "=r"(d) : "f"(odd), "f"(even));
    return d;
}

// ---------------- trivial elementwise kernels ------------------------------
__global__ void embed_kernel(const float* __restrict__ x,
                             const float* __restrict__ w,
                             const float* __restrict__ b,
                             float* __restrict__ h, int* __restrict__ cnt,
                             int n) {
    int i = blockIdx.x * blockDim.x + threadIdx.x;
    if (i < n) cnt[i] = 0;
    if (i < n * H) {
        int node = i >> 6, j = i & 63;
        h[i] = fmaf(x[node], w[j], b[j]);
    }
}

__global__ void count_kernel(const int* __restrict__ dst, int* cnt, int e) {
    int i = blockIdx.x * blockDim.x + threadIdx.x;
    if (i < e) atomicAdd(&cnt[dst[i]], 1);
}

// prefix scan of cnt + precompute per-layer fp16 B = W2^T (stride 72)
__global__ void scan_prep_kernel(const int* __restrict__ cnt,
                                 int* __restrict__ cursor, int n,
                                 const float* __restrict__ mw2, int L) {
    int tid = threadIdx.x;
    int total = L * H * H;
    for (int i = tid; i < total; i += 1024) {
        int l = i >> 12, rem = i & 4095;
        int nn = rem >> 6, k = rem & 63;
        float w = mw2[(size_t)l * 4096 + k * 64 + nn];
        g_Bh[(size_t)l * (64 * 72) + nn * 72 + k] = __float2half_rn(w);
    }
    __shared__ int s[1024];
    int chunk = (n + 1023) >> 10;
    int lo = tid * chunk;
    int hi = min(lo + chunk, n);
    int sum = 0;
    for (int i = lo; i < hi; i++) sum += cnt[i];
    s[tid] = sum;
    __syncthreads();
    for (int off = 1; off < 1024; off <<= 1) {
        int v = (tid >= off) ? s[tid - off] : 0;
        __syncthreads();
        s[tid] += v;
        __syncthreads();
    }
    int run = s[tid] - sum;
    for (int i = lo; i < hi; i++) { cursor[i] = run; run += cnt[i]; }
}

// scatter (build perm) + init aggr to encoded +inf
__global__ void scatter_kernel(const int* __restrict__ dst, int* cursor,
                               int* perm, unsigned* __restrict__ aggr,
                               int e, int nH4) {
    int i = blockIdx.x * blockDim.x + threadIdx.x;
    if (i < e) {
        int p = atomicAdd(&cursor[dst[i]], 1);
        perm[p] = i;
    }
    uint4 f = make_uint4(~0u, ~0u, ~0u, ~0u);
    for (int j = i; j < nH4; j += gridDim.x * blockDim.x)
        ((uint4*)aggr)[j] = f;
}

__global__ void fc_kernel(const float* __restrict__ h,
                          const float* __restrict__ fcw,
                          const float* __restrict__ fcb,
                          float* __restrict__ out, int n) {
    int i = blockIdx.x * blockDim.x + threadIdx.x;
    if (i >= n) return;
    const float4* h4 = (const float4*)(h + (size_t)i * H);
    const float4* w4 = (const float4*)fcw;
    float s = 0.f;
#pragma unroll
    for (int q = 0; q < 16; q++) {
        float4 a = h4[q], w = w4[q];
        s += a.x * w.x + a.y * w.y + a.z * w.z + a.w * w.w;
    }
    out[i] = s + fcb[0];
}

// -------- node GEMM (fp32 f32x2 path; DECODE fuses aggr finalize) ----------
template <int K>
__device__ __forceinline__ void gemm_body(const float* Xs, const float* Ws,
                                          int ty, int tx, u64 acc2[8][4]) {
    const float4* Xs4 = (const float4*)Xs;
#pragma unroll 4
    for (int k = 0; k < K; k++) {
        float4 a0 = Xs4[k * 32 + ty * 2];
        float4 a1 = Xs4[k * 32 + ty * 2 + 1];
        const ulonglong2* Wp = (const ulonglong2*)(Ws + k * 64 + tx * 8);
        ulonglong2 w01 = Wp[0];
        ulonglong2 w23 = Wp[1];
        u64 aa[8] = {pk_dup(a0.x), pk_dup(a0.y), pk_dup(a0.z), pk_dup(a0.w),
                     pk_dup(a1.x), pk_dup(a1.y), pk_dup(a1.z), pk_dup(a1.w)};
#pragma unroll
        for (int r = 0; r < 8; r++) {
            fma2(acc2[r][0], aa[r], w01.x);
            fma2(acc2[r][1], aa[r], w01.y);
            fma2(acc2[r][2], aa[r], w23.x);
            fma2(acc2[r][3], aa[r], w23.y);
        }
    }
}

template <int K, bool RELU, bool DECODE>
__global__ void __launch_bounds__(128)
node_gemm(const float* __restrict__ X1, const void* __restrict__ X2p,
          const float* __restrict__ W, const float* __restrict__ bias,
          float* __restrict__ C, int Nn,
          const float* __restrict__ b2g, unsigned* __restrict__ aggrw) {
    extern __shared__ float sm[];
    float* Ws = sm;
    float* Xs = sm + K * 64;
    float* b2s = sm + K * 64 + K * 128;   // 64 floats (DECODE only)
    int tid = threadIdx.x;
    int n0 = blockIdx.x * 128;
    {
        const float4* W4 = (const float4*)W;
        float4* Ws4 = (float4*)Ws;
#pragma unroll
        for (int i = 0; i < K / 8; i++) Ws4[tid + i * 128] = W4[tid + i * 128];
    }
    int n = min(n0 + tid, Nn - 1);
    {
        const float4* X14 = (const float4*)(X1 + (size_t)n * H);
#pragma unroll
        for (int q = 0; q < 16; q++) {
            float4 v = X14[q];
            Xs[(4 * q + 0) * 128 + tid] = v.x;
            Xs[(4 * q + 1) * 128 + tid] = v.y;
            Xs[(4 * q + 2) * 128 + tid] = v.z;
            Xs[(4 * q + 3) * 128 + tid] = v.w;
        }
    }
    if (DECODE) {
        if (tid < 64) b2s[tid] = b2g[tid];
        __syncthreads();
    }
    if (K == 128) {
        if (DECODE) {
            const uint4* X24 = (const uint4*)((const unsigned*)X2p +
                                              (size_t)n * H);
#pragma unroll
            for (int q = 0; q < 16; q++) {
                uint4 u = X24[q];
                float4 v;
                v.x = (u.x >= 0xFF800000u) ? 0.f : (fdec(u.x) + b2s[4 * q + 0]);
                v.y = (u.y >= 0xFF800000u) ? 0.f : (fdec(u.y) + b2s[4 * q + 1]);
                v.z = (u.z >= 0xFF800000u) ? 0.f : (fdec(u.z) + b2s[4 * q + 2]);
                v.w = (u.w >= 0xFF800000u) ? 0.f : (fdec(u.w) + b2s[4 * q + 3]);
                Xs[(64 + 4 * q + 0) * 128 + tid] = v.x;
                Xs[(64 + 4 * q + 1) * 128 + tid] = v.y;
                Xs[(64 + 4 * q + 2) * 128 + tid] = v.z;
                Xs[(64 + 4 * q + 3) * 128 + tid] = v.w;
            }
            // re-poison aggr for next layer (owner thread only; safe at tail)
            if (n0 + tid < Nn) {
                uint4 p = make_uint4(~0u, ~0u, ~0u, ~0u);
                uint4* A4 = (uint4*)(aggrw + (size_t)n * H);
#pragma unroll
                for (int q = 0; q < 16; q++) A4[q] = p;
            }
        } else {
            const float4* X24 = (const float4*)((const float*)X2p +
                                                (size_t)n * H);
#pragma unroll
            for (int q = 0; q < 16; q++) {
                float4 v = X24[q];
                Xs[(64 + 4 * q + 0) * 128 + tid] = v.x;
                Xs[(64 + 4 * q + 1) * 128 + tid] = v.y;
                Xs[(64 + 4 * q + 2) * 128 + tid] = v.z;
                Xs[(64 + 4 * q + 3) * 128 + tid] = v.w;
            }
        }
    }
    __syncthreads();
    int ty = tid >> 3, tx = tid & 7;
    u64 acc2[8][4];
#pragma unroll
    for (int r = 0; r < 8; r++)
#pragma unroll
        for (int c = 0; c < 4; c++) acc2[r][c] = 0ull;
    gemm_body<K>(Xs, Ws, ty, tx, acc2);
    float bb[8];
#pragma unroll
    for (int c = 0; c < 8; c++) bb[c] = bias[tx * 8 + c];
#pragma unroll
    for (int r = 0; r < 8; r++) {
        int nr = n0 + ty * 8 + r;
        if (nr < Nn) {
            float o[8];
            unpk(o[0], o[1], acc2[r][0]);
            unpk(o[2], o[3], acc2[r][1]);
            unpk(o[4], o[5], acc2[r][2]);
            unpk(o[6], o[7], acc2[r][3]);
            float4 o0, o1;
            o0.x = o[0] + bb[0]; o0.y = o[1] + bb[1];
            o0.z = o[2] + bb[2]; o0.w = o[3] + bb[3];
            o1.x = o[4] + bb[4]; o1.y = o[5] + bb[5];
            o1.z = o[6] + bb[6]; o1.w = o[7] + bb[7];
            if (RELU) {
                o0.x = fmaxf(o0.x, 0.f); o0.y = fmaxf(o0.y, 0.f);
                o0.z = fmaxf(o0.z, 0.f); o0.w = fmaxf(o0.w, 0.f);
                o1.x = fmaxf(o1.x, 0.f); o1.y = fmaxf(o1.y, 0.f);
                o1.z = fmaxf(o1.z, 0.f); o1.w = fmaxf(o1.w, 0.f);
            }
            float4* C4 = (float4*)(C + (size_t)nr * H);
            C4[tx * 2] = o0;
            C4[tx * 2 + 1] = o1;
        }
    }
}

// ---------------- HMMA edge kernel (persistent, single-term fp16) ----------
// Per 128-edge tile: T = relu(A[src]+ev*we) -> fp16 rows (stride 72);
// D[128,64] = T@B^T via mma.sync m16n8k16 (fp32 acc; rounding ~2^-11/layer,
// damped ~40x by min-aggregation + contractive MLPs -> final ~2e-5);
// D staged to XOR-swizzled SMEM -> segmented min by sorted dst -> atomicMin.
// Occupancy pinned at 4 CTAs/SM: at 5 the 96-reg budget spills the 64-reg
// accumulator file to local memory (R6 regression).
#define TH_OFF   0            // 128 x 72 f16 = 18432 B (Ds overlay: 32768 B)
#define BH_OFF   32768        // 64 x 72 f16 = 9216 B
#define WES_OFF  41984        // 64 f32
#define DST_OFF  42240        // 128 int
#define SMEM_EDGE 42752

__global__ void __launch_bounds__(128, 4)
edge_mma_kernel(const float* __restrict__ Ag, const int* __restrict__ src,
                const int* __restrict__ dstp, const float* __restrict__ ea,
                const int* __restrict__ perm, const float* __restrict__ weg,
                const __half* __restrict__ Bh_g,
                unsigned* __restrict__ aggr, int E, int ntiles) {
    extern __shared__ char smc[];
    uint32_t sb = smem_u32(smc);
    int tid = threadIdx.x;
    int lane = tid & 31;
    int wid = tid >> 5;

    // one-time: copy B (576 uint4) + we into smem
    {
        const uint4* s4 = (const uint4*)Bh_g;
        uint4* d4 = (uint4*)(smc + BH_OFF);
        for (int i = tid; i < 576; i += 128) d4[i] = s4[i];
        if (tid < 64) ((float*)(smc + WES_OFF))[tid] = weg[tid];
    }
    __syncthreads();

    const float* wes = (const float*)(smc + WES_OFF);
    int* dstL = (int*)(smc + DST_OFF);
    float* Ds = (float*)smc;   // overlays T after mma reads complete

    int m0 = wid * 32;
    // ldmatrix lane-address components
    uint32_t aRow = (lane & 7) + 8u * ((lane >> 3) & 1);
    uint32_t aKoff = 16u * (lane >> 4);
    uint32_t bBase = 144u * (8u * ((lane >> 4) & 1) + (lane & 7)) +
                     16u * ((lane >> 3) & 1);

    for (int tile = blockIdx.x; tile < ntiles; tile += gridDim.x) {
        // ---- gather + relu + fp16 convert -> T rows (144B stride) ----
        {
            int slot = tile * 128 + tid;
            int eidx = perm[min(slot, E - 1)];
            int s = src[eidx];
            float ev = ea[eidx];
            dstL[tid] = (slot < E) ? dstp[eidx] : -1;
            const float4* A4 = (const float4*)(Ag + (size_t)s * H);
            char* thRow = smc + TH_OFF + tid * 144;
#pragma unroll
            for (int q = 0; q < 8; q++) {
                float4 a0 = A4[2 * q], a1 = A4[2 * q + 1];
                float v[8];
                v[0] = fmaxf(fmaf(ev, wes[q * 8 + 0], a0.x), 0.f);
                v[1] = fmaxf(fmaf(ev, wes[q * 8 + 1], a0.y), 0.f);
                v[2] = fmaxf(fmaf(ev, wes[q * 8 + 2], a0.z), 0.f);
                v[3] = fmaxf(fmaf(ev, wes[q * 8 + 3], a0.w), 0.f);
                v[4] = fmaxf(fmaf(ev, wes[q * 8 + 4], a1.x), 0.f);
                v[5] = fmaxf(fmaf(ev, wes[q * 8 + 5], a1.y), 0.f);
                v[6] = fmaxf(fmaf(ev, wes[q * 8 + 6], a1.z), 0.f);
                v[7] = fmaxf(fmaf(ev, wes[q * 8 + 7], a1.w), 0.f);
                uint4 hp;
                hp.x = cvt2h(v[1], v[0]);
                hp.y = cvt2h(v[3], v[2]);
                hp.z = cvt2h(v[5], v[4]);
                hp.w = cvt2h(v[7], v[6]);
                *(uint4*)(thRow + q * 16) = hp;
            }
        }
        __syncthreads();

        // ---- warp MMA: rows m0..m0+31, 4 k-steps, single fp16 term ----
        float acc[2][8][4];
#pragma unroll
        for (int mt = 0; mt < 2; mt++)
#pragma unroll
            for (int nt = 0; nt < 8; nt++)
#pragma unroll
                for (int c = 0; c < 4; c++) acc[mt][nt][c] = 0.f;

#pragma unroll
        for (int ks = 0; ks < 4; ks++) {
            uint32_t ah0[4], ah1[4];
            ldsm4(ah0, sb + TH_OFF + 144u * (m0 + aRow) + 32u * ks + aKoff);
            ldsm4(ah1, sb + TH_OFF + 144u * (m0 + 16 + aRow) + 32u * ks + aKoff);
#pragma unroll
            for (int ntp = 0; ntp < 4; ntp++) {
                uint32_t b4[4];
                ldsm4(b4, sb + BH_OFF + bBase + 2304u * ntp + 32u * ks);
                mma16816h(acc[0][2 * ntp], ah0, b4[0], b4[1]);
                mma16816h(acc[1][2 * ntp], ah1, b4[0], b4[1]);
                mma16816h(acc[0][2 * ntp + 1], ah0, b4[2], b4[3]);
                mma16816h(acc[1][2 * ntp + 1], ah1, b4[2], b4[3]);
            }
        }
        __syncthreads();   // T reads done before Ds overlay writes

        // ---- stage D to swizzled SMEM: float4 slot = e*16 + (c4^(e&15)) ----
#pragma unroll
        for (int mt = 0; mt < 2; mt++) {
            int eb = m0 + mt * 16 + (lane >> 2);
            int h2i = lane & 1;
            int c4b = (lane & 3) >> 1;
#pragma unroll
            for (int nt = 0; nt < 8; nt++) {
                int c4 = nt * 2 + c4b;
                float2 v0 = make_float2(acc[mt][nt][0], acc[mt][nt][1]);
                float2 v1 = make_float2(acc[mt][nt][2], acc[mt][nt][3]);
                int e0 = eb, e1 = eb + 8;
                ((float2*)(Ds + (e0 * 16 + (c4 ^ (e0 & 15))) * 4))[h2i] = v0;
                ((float2*)(Ds + (e1 * 16 + (c4 ^ (e1 & 15))) * 4))[h2i] = v1;
            }
        }
        __syncthreads();

        // ---- epilogue: segmented min over 8 sorted edges, atomicMin ----
        {
            const float4* Ds4 = (const float4*)Ds;
            int ty = tid >> 3, tx = tid & 7;
            int cur = -2;
            float4 mA, mB;
#pragma unroll
            for (int r = 0; r < 8; r++) {
                int e = ty * 8 + r;
                int d = dstL[e];
                float4 a = Ds4[e * 16 + (tx ^ (e & 15))];
                float4 b = Ds4[e * 16 + ((8 + tx) ^ (e & 15))];
                if (r == 0 || d != cur) {
                    if (r > 0 && cur >= 0) {
                        unsigned* p0 = aggr + (size_t)cur * H + tx * 4;
                        atomicMin(p0 + 0, fenc(mA.x));
                        atomicMin(p0 + 1, fenc(mA.y));
                        atomicMin(p0 + 2, fenc(mA.z));
                        atomicMin(p0 + 3, fenc(mA.w));
                        unsigned* p1 = p0 + 32;
                        atomicMin(p1 + 0, fenc(mB.x));
                        atomicMin(p1 + 1, fenc(mB.y));
                        atomicMin(p1 + 2, fenc(mB.z));
                        atomicMin(p1 + 3, fenc(mB.w));
                    }
                    cur = d;
                    mA = a; mB = b;
                } else {
                    mA.x = fminf(mA.x, a.x); mA.y = fminf(mA.y, a.y);
                    mA.z = fminf(mA.z, a.z); mA.w = fminf(mA.w, a.w);
                    mB.x = fminf(mB.x, b.x); mB.y = fminf(mB.y, b.y);
                    mB.z = fminf(mB.z, b.z); mB.w = fminf(mB.w, b.w);
                }
            }
            if (cur >= 0) {
                unsigned* p0 = aggr + (size_t)cur * H + tx * 4;
                atomicMin(p0 + 0, fenc(mA.x));
                atomicMin(p0 + 1, fenc(mA.y));
                atomicMin(p0 + 2, fenc(mA.z));
                atomicMin(p0 + 3, fenc(mA.w));
                unsigned* p1 = p0 + 32;
                atomicMin(p1 + 0, fenc(mB.x));
                atomicMin(p1 + 1, fenc(mB.y));
                atomicMin(p1 + 2, fenc(mB.z));
                atomicMin(p1 + 3, fenc(mB.w));
            }
        }
        __syncthreads();   // Ds/dstL dead before next tile's writes
    }
}

// ---------------- host launch ----------------------------------------------
extern "C" void kernel_launch(void* const* d_in, const int* in_sizes, int n_in,
                              void* d_out, int out_size) {
    const float* x    = (const float*)d_in[0];
    const int*   ei   = (const int*)d_in[1];
    const float* ea   = (const float*)d_in[2];
    const float* embw = (const float*)d_in[3];
    const float* embb = (const float*)d_in[4];
    const float* mw1  = (const float*)d_in[5];
    const float* mb1  = (const float*)d_in[6];
    const float* mw2  = (const float*)d_in[7];
    const float* mb2  = (const float*)d_in[8];
    const float* uw1  = (const float*)d_in[9];
    const float* ub1  = (const float*)d_in[10];
    const float* uw2  = (const float*)d_in[11];
    const float* ub2  = (const float*)d_in[12];
    const float* fcw  = (const float*)d_in[13];
    const float* fcb  = (const float*)d_in[14];
    float* out = (float*)d_out;

    int N = in_sizes[0];
    int E = in_sizes[2];
    int L = in_sizes[6] / H;
    const int* src = ei;
    const int* dstp = ei + E;

    float* hbuf; float* Abuf; unsigned* aggr;
    int* cnt; int* cursor; int* perm;
    __half* Bh;
    cudaGetSymbolAddress((void**)&hbuf, g_h);
    cudaGetSymbolAddress((void**)&Abuf, g_A);
    cudaGetSymbolAddress((void**)&aggr, g_aggr);
    cudaGetSymbolAddress((void**)&cnt, g_cnt);
    cudaGetSymbolAddress((void**)&cursor, g_cursor);
    cudaGetSymbolAddress((void**)&perm, g_perm);
    cudaGetSymbolAddress((void**)&Bh, g_Bh);

    const size_t sm64  = (64 * 64 + 64 * 128) * 4;
    const size_t sm128 = (128 * 64 + 128 * 128 + 64) * 4;
    cudaFuncSetAttribute(edge_mma_kernel,
                         cudaFuncAttributeMaxDynamicSharedMemorySize, SMEM_EDGE);
    cudaFuncSetAttribute((node_gemm<64, false, false>),
                         cudaFuncAttributeMaxDynamicSharedMemorySize, (int)sm64);
    cudaFuncSetAttribute((node_gemm<128, true, true>),
                         cudaFuncAttributeMaxDynamicSharedMemorySize, (int)sm128);

    int ntiles = (E + 127) / 128;
    int edgeGrid = 148 * 4;
    if (edgeGrid > ntiles) edgeGrid = ntiles;
    int nodeBlocks = (N + 127) / 128;

    // embedding (+ zero cnt)
    embed_kernel<<<(N * H + 255) / 256, 256>>>(x, embw, embb, hbuf, cnt, N);
    // counting sort by dst (+ B fp16 prep, + aggr poison)
    count_kernel<<<(E + 255) / 256, 256>>>(dstp, cnt, E);
    scan_prep_kernel<<<1, 1024>>>(cnt, cursor, N, mw2, L);
    scatter_kernel<<<(E + 255) / 256, 256>>>(dstp, cursor, perm, aggr, E,
                                             N * H / 4);

    for (int l = 0; l < L; l++) {
        const float* w1 = mw1 + (size_t)l * (H + 1) * H;   // [65,64]
        // A = h @ W1[:64] + b1  (per-node hoist of per-edge msg layer 1)
        node_gemm<64, false, false><<<nodeBlocks, 128, sm64>>>(
            hbuf, nullptr, w1, mb1 + (size_t)l * H, Abuf, N, nullptr, nullptr);
        // tensor-pipe edge message + scatter-min
        edge_mma_kernel<<<edgeGrid, 128, SMEM_EDGE>>>(
            Abuf, src, dstp, ea, perm, w1 + (size_t)H * H,
            Bh + (size_t)l * (64 * 72), aggr, E, ntiles);
        // update MLP layer 1 (fused aggr decode + b2 + re-poison)
        node_gemm<128, true, true><<<nodeBlocks, 128, sm128>>>(
            hbuf, aggr, uw1 + (size_t)l * 2 * H * H, ub1 + (size_t)l * H,
            Abuf, N, mb2 + (size_t)l * H, aggr);
        // update MLP layer 2
        node_gemm<64, false, false><<<nodeBlocks, 128, sm64>>>(
            Abuf, nullptr, uw2 + (size_t)l * H * H, ub2 + (size_t)l * H,
            hbuf, N, nullptr, nullptr);
    }

    fc_kernel<<<(N + 255) / 256, 256>>>(hbuf, fcw, fcb, out, N);
}

// round 8
// speedup vs baseline: 1.1892x; 1.0025x over previous
#include <cuda_runtime.h>
#include <cuda_bf16.h>
#include <cuda_fp16.h>
#include <cstdint>

#define H 64
#define MAXN 100000
#define MAXE 1600000
#define MAXL 8

typedef unsigned long long u64;

// ---------------- device scratch (static: no dynamic allocation allowed) ----
__device__ float         g_h[(size_t)MAXN * H];
__device__ float         g_A[(size_t)MAXN * H];
__device__ unsigned int  g_aggr[(size_t)MAXN * H];
__device__ int           g_cnt[MAXN];
__device__ int           g_cursor[MAXN];
__device__ int           g_perm[MAXE];
__device__ __half        g_Bh[MAXL * 64 * 72];  // per-layer W2^T fp16, [n][72] rows

// order-preserving float<->uint encoding for atomic min
__device__ __forceinline__ unsigned fenc(float f) {
    unsigned u = __float_as_uint(f);
    return (u & 0x80000000u) ? ~u : (u | 0x80000000u);
}
__device__ __forceinline__ float fdec(unsigned u) {
    return (u & 0x80000000u) ? __uint_as_float(u & 0x7FFFFFFFu)
                             : __uint_as_float(~u);
}

// -------- packed f32x2 helpers (node GEMMs) --------------------------------
__device__ __forceinline__ u64 pk_dup(float x) {
    u64 r;
    asm("mov.b64 %0, {%1,%1};" : "=l"(r) : "f"(x));
    return r;
}
__device__ __forceinline__ void fma2(u64& d, u64 a, u64 b) {
    asm("fma.rn.f32x2 %0, %1, %2, %3;" : "=l"(d) : "l"(a), "l"(b), "l"(d));
}
__device__ __forceinline__ void unpk(float& lo, float& hi, u64 v) {
    asm("mov.b64 {%0,%1}, %2;" : "=f"(lo), "=f"(hi) : "l"(v));
}

// -------- warp-mma plumbing (plain sm_80+ PTX) -----------------------------
__device__ __forceinline__ uint32_t smem_u32(const void* p) {
    uint32_t a;
    asm("{ .reg .u64 t; cvta.to.shared.u64 t, %1; cvt.u32.u64 %0, t; }"
        : "=r"(a) : "l"(p));
    return a;
}
__device__ __forceinline__ void ldsm4(uint32_t (&r)[4], uint32_t addr) {
    asm volatile("ldmatrix.sync.aligned.m8n8.x4.shared.b16 {%0,%1,%2,%3}, [%4];"
                 : "=r"(r[0]), "=r"(r[1]), "=r"(r[2]), "=r"(r[3]) : "r"(addr));
}
__device__ __forceinline__ void mma16816h(float (&d)[4], const uint32_t (&a)[4],
                                          uint32_t b0, uint32_t b1) {
    asm volatile(
        "mma.sync.aligned.m16n8k16.row.col.f32.f16.f16.f32 "
        "{%0,%1,%2,%3}, {%4,%5,%6,%7}, {%8,%9}, {%0,%1,%2,%3};"
        : "+f"(d[0]), "+f"(d[1]), "+f"(d[2]), "+f"(d[3])
        : "r"(a[0]), "r"(a[1]), "r"(a[2]), "r"(a[3]), "r"(b0), "r"(b1));
}
// pack f16(even)|f16(odd)<<16
__device__ __forceinline__ uint32_t cvt2h(float odd, float even) {
    uint32_t d;
    asm("cvt.rn.f16x2.f32 %0, %1, %2;" : "=r"(d) : "f"(odd), "f"(even));
    return d;
}

// ---------------- trivial elementwise kernels ------------------------------
__global__ void embed_kernel(const float* __restrict__ x,
                             const float* __restrict__ w,
                             const float* __restrict__ b,
                             float* __restrict__ h, int* __restrict__ cnt,
                             int n) {
    int i = blockIdx.x * blockDim.x + threadIdx.x;
    if (i < n) cnt[i] = 0;
    if (i < n * H) {
        int node = i >> 6, j = i & 63;
        h[i] = fmaf(x[node], w[j], b[j]);
    }
}

__global__ void count_kernel(const int* __restrict__ dst, int* cnt, int e) {
    int i = blockIdx.x * blockDim.x + threadIdx.x;
    if (i < e) atomicAdd(&cnt[dst[i]], 1);
}

// prefix scan of cnt + precompute per-layer fp16 B = W2^T (stride 72)
__global__ void scan_prep_kernel(const int* __restrict__ cnt,
                                 int* __restrict__ cursor, int n,
                                 const float* __restrict__ mw2, int L) {
    int tid = threadIdx.x;
    int total = L * H * H;
    for (int i = tid; i < total; i += 1024) {
        int l = i >> 12, rem = i & 4095;
        int nn = rem >> 6, k = rem & 63;
        float w = mw2[(size_t)l * 4096 + k * 64 + nn];
        g_Bh[(size_t)l * (64 * 72) + nn * 72 + k] = __float2half_rn(w);
    }
    __shared__ int s[1024];
    int chunk = (n + 1023) >> 10;
    int lo = tid * chunk;
    int hi = min(lo + chunk, n);
    int sum = 0;
    for (int i = lo; i < hi; i++) sum += cnt[i];
    s[tid] = sum;
    __syncthreads();
    for (int off = 1; off < 1024; off <<= 1) {
        int v = (tid >= off) ? s[tid - off] : 0;
        __syncthreads();
        s[tid] += v;
        __syncthreads();
    }
    int run = s[tid] - sum;
    for (int i = lo; i < hi; i++) { cursor[i] = run; run += cnt[i]; }
}

// scatter (build perm) + init aggr to encoded +inf
__global__ void scatter_kernel(const int* __restrict__ dst, int* cursor,
                               int* perm, unsigned* __restrict__ aggr,
                               int e, int nH4) {
    int i = blockIdx.x * blockDim.x + threadIdx.x;
    if (i < e) {
        int p = atomicAdd(&cursor[dst[i]], 1);
        perm[p] = i;
    }
    uint4 f = make_uint4(~0u, ~0u, ~0u, ~0u);
    for (int j = i; j < nH4; j += gridDim.x * blockDim.x)
        ((uint4*)aggr)[j] = f;
}

__global__ void fc_kernel(const float* __restrict__ h,
                          const float* __restrict__ fcw,
                          const float* __restrict__ fcb,
                          float* __restrict__ out, int n) {
    int i = blockIdx.x * blockDim.x + threadIdx.x;
    if (i >= n) return;
    const float4* h4 = (const float4*)(h + (size_t)i * H);
    const float4* w4 = (const float4*)fcw;
    float s = 0.f;
#pragma unroll
    for (int q = 0; q < 16; q++) {
        float4 a = h4[q], w = w4[q];
        s += a.x * w.x + a.y * w.y + a.z * w.z + a.w * w.w;
    }
    out[i] = s + fcb[0];
}

// -------- node GEMM (fp32 f32x2 path; DECODE fuses aggr finalize) ----------
template <int K>
__device__ __forceinline__ void gemm_body(const float* Xs, const float* Ws,
                                          int ty, int tx, u64 acc2[8][4]) {
    const float4* Xs4 = (const float4*)Xs;
#pragma unroll 4
    for (int k = 0; k < K; k++) {
        float4 a0 = Xs4[k * 32 + ty * 2];
        float4 a1 = Xs4[k * 32 + ty * 2 + 1];
        const ulonglong2* Wp = (const ulonglong2*)(Ws + k * 64 + tx * 8);
        ulonglong2 w01 = Wp[0];
        ulonglong2 w23 = Wp[1];
        u64 aa[8] = {pk_dup(a0.x), pk_dup(a0.y), pk_dup(a0.z), pk_dup(a0.w),
                     pk_dup(a1.x), pk_dup(a1.y), pk_dup(a1.z), pk_dup(a1.w)};
#pragma unroll
        for (int r = 0; r < 8; r++) {
            fma2(acc2[r][0], aa[r], w01.x);
            fma2(acc2[r][1], aa[r], w01.y);
            fma2(acc2[r][2], aa[r], w23.x);
            fma2(acc2[r][3], aa[r], w23.y);
        }
    }
}

template <int K, bool RELU, bool DECODE>
__global__ void __launch_bounds__(128)
node_gemm(const float* __restrict__ X1, const void* __restrict__ X2p,
          const float* __restrict__ W, const float* __restrict__ bias,
          float* __restrict__ C, int Nn,
          const float* __restrict__ b2g, unsigned* __restrict__ aggrw) {
    extern __shared__ float sm[];
    float* Ws = sm;
    float* Xs = sm + K * 64;
    float* b2s = sm + K * 64 + K * 128;   // 64 floats (DECODE only)
    int tid = threadIdx.x;
    int n0 = blockIdx.x * 128;
    {
        const float4* W4 = (const float4*)W;
        float4* Ws4 = (float4*)Ws;
#pragma unroll
        for (int i = 0; i < K / 8; i++) Ws4[tid + i * 128] = W4[tid + i * 128];
    }
    int n = min(n0 + tid, Nn - 1);
    {
        const float4* X14 = (const float4*)(X1 + (size_t)n * H);
#pragma unroll
        for (int q = 0; q < 16; q++) {
            float4 v = X14[q];
            Xs[(4 * q + 0) * 128 + tid] = v.x;
            Xs[(4 * q + 1) * 128 + tid] = v.y;
            Xs[(4 * q + 2) * 128 + tid] = v.z;
            Xs[(4 * q + 3) * 128 + tid] = v.w;
        }
    }
    if (DECODE) {
        if (tid < 64) b2s[tid] = b2g[tid];
        __syncthreads();
    }
    if (K == 128) {
        if (DECODE) {
            const uint4* X24 = (const uint4*)((const unsigned*)X2p +
                                              (size_t)n * H);
#pragma unroll
            for (int q = 0; q < 16; q++) {
                uint4 u = X24[q];
                float4 v;
                v.x = (u.x >= 0xFF800000u) ? 0.f : (fdec(u.x) + b2s[4 * q + 0]);
                v.y = (u.y >= 0xFF800000u) ? 0.f : (fdec(u.y) + b2s[4 * q + 1]);
                v.z = (u.z >= 0xFF800000u) ? 0.f : (fdec(u.z) + b2s[4 * q + 2]);
                v.w = (u.w >= 0xFF800000u) ? 0.f : (fdec(u.w) + b2s[4 * q + 3]);
                Xs[(64 + 4 * q + 0) * 128 + tid] = v.x;
                Xs[(64 + 4 * q + 1) * 128 + tid] = v.y;
                Xs[(64 + 4 * q + 2) * 128 + tid] = v.z;
                Xs[(64 + 4 * q + 3) * 128 + tid] = v.w;
            }
            // re-poison aggr for next layer (owner thread only; safe at tail)
            if (n0 + tid < Nn) {
                uint4 p = make_uint4(~0u, ~0u, ~0u, ~0u);
                uint4* A4 = (uint4*)(aggrw + (size_t)n * H);
#pragma unroll
                for (int q = 0; q < 16; q++) A4[q] = p;
            }
        } else {
            const float4* X24 = (const float4*)((const float*)X2p +
                                                (size_t)n * H);
#pragma unroll
            for (int q = 0; q < 16; q++) {
                float4 v = X24[q];
                Xs[(64 + 4 * q + 0) * 128 + tid] = v.x;
                Xs[(64 + 4 * q + 1) * 128 + tid] = v.y;
                Xs[(64 + 4 * q + 2) * 128 + tid] = v.z;
                Xs[(64 + 4 * q + 3) * 128 + tid] = v.w;
            }
        }
    }
    __syncthreads();
    int ty = tid >> 3, tx = tid & 7;
    u64 acc2[8][4];
#pragma unroll
    for (int r = 0; r < 8; r++)
#pragma unroll
        for (int c = 0; c < 4; c++) acc2[r][c] = 0ull;
    gemm_body<K>(Xs, Ws, ty, tx, acc2);
    float bb[8];
#pragma unroll
    for (int c = 0; c < 8; c++) bb[c] = bias[tx * 8 + c];
#pragma unroll
    for (int r = 0; r < 8; r++) {
        int nr = n0 + ty * 8 + r;
        if (nr < Nn) {
            float o[8];
            unpk(o[0], o[1], acc2[r][0]);
            unpk(o[2], o[3], acc2[r][1]);
            unpk(o[4], o[5], acc2[r][2]);
            unpk(o[6], o[7], acc2[r][3]);
            float4 o0, o1;
            o0.x = o[0] + bb[0]; o0.y = o[1] + bb[1];
            o0.z = o[2] + bb[2]; o0.w = o[3] + bb[3];
            o1.x = o[4] + bb[4]; o1.y = o[5] + bb[5];
            o1.z = o[6] + bb[6]; o1.w = o[7] + bb[7];
            if (RELU) {
                o0.x = fmaxf(o0.x, 0.f); o0.y = fmaxf(o0.y, 0.f);
                o0.z = fmaxf(o0.z, 0.f); o0.w = fmaxf(o0.w, 0.f);
                o1.x = fmaxf(o1.x, 0.f); o1.y = fmaxf(o1.y, 0.f);
                o1.z = fmaxf(o1.z, 0.f); o1.w = fmaxf(o1.w, 0.f);
            }
            float4* C4 = (float4*)(C + (size_t)nr * H);
            C4[tx * 2] = o0;
            C4[tx * 2 + 1] = o1;
        }
    }
}

// ---------------- HMMA edge kernel (persistent, warp-independent tiles) ----
// Each WARP owns a 32-edge tile in a private 8KB smem region: gather+relu+
// fp16 -> T rows (144B stride) -> 64 mma.sync (D[32,64]=T@B^T, fp32 acc) ->
// XOR-swizzled Ds transpose -> segmented min by sorted dst -> atomicMin.
// Only __syncwarp between phases: a gather straggler stalls 32 threads, not
// 128, and 16 resident warps/SM pipeline phases against each other.
// Segments still split at 8-edge boundaries -> bitwise-identical to R7.
#define TW_STRIDE 8192        // per-warp union: T (32x144=4608B) / Ds (8192B)
#define BH_OFF   32768        // 64 x 72 f16 = 9216 B (CTA-shared)
#define WES_OFF  41984        // 64 f32
#define DST_OFF  42240        // 4 warps x 32 int
#define SMEM_EDGE 42752

__global__ void __launch_bounds__(128, 4)
edge_mma_kernel(const float* __restrict__ Ag, const int* __restrict__ src,
                const int* __restrict__ dstp, const float* __restrict__ ea,
                const int* __restrict__ perm, const float* __restrict__ weg,
                const __half* __restrict__ Bh_g,
                unsigned* __restrict__ aggr, int E, int nt32) {
    extern __shared__ char smc[];
    uint32_t sb = smem_u32(smc);
    int tid = threadIdx.x;
    int lane = tid & 31;
    int wid = tid >> 5;

    // one-time: copy B (576 uint4) + we into smem (CTA-shared, read-only)
    {
        const uint4* s4 = (const uint4*)Bh_g;
        uint4* d4 = (uint4*)(smc + BH_OFF);
        for (int i = tid; i < 576; i += 128) d4[i] = s4[i];
        if (tid < 64) ((float*)(smc + WES_OFF))[tid] = weg[tid];
    }
    __syncthreads();

    const float* wes = (const float*)(smc + WES_OFF);
    char* Tw = smc + wid * TW_STRIDE;
    uint32_t sbT = sb + wid * TW_STRIDE;
    float* Ds = (float*)Tw;                       // overlay after mma reads
    int* dstw = (int*)(smc + DST_OFF + wid * 128);

    // ldmatrix lane-address components
    uint32_t aRow = (lane & 7) + 8u * ((lane >> 3) & 1);
    uint32_t aKoff = 16u * (lane >> 4);
    uint32_t bBase = 144u * (8u * ((lane >> 4) & 1) + (lane & 7)) +
                     16u * ((lane >> 3) & 1);

    for (int t = blockIdx.x * 4 + wid; t < nt32; t += gridDim.x * 4) {
        // ---- gather + relu + fp16 convert -> T rows (144B stride) ----
        {
            int slot = t * 32 + lane;
            int eidx = perm[min(slot, E - 1)];
            int s = src[eidx];
            float ev = ea[eidx];
            dstw[lane] = (slot < E) ? dstp[eidx] : -1;
            const float4* A4 = (const float4*)(Ag + (size_t)s * H);
            char* thRow = Tw + lane * 144;
#pragma unroll
            for (int q = 0; q < 8; q++) {
                float4 a0 = A4[2 * q], a1 = A4[2 * q + 1];
                float v[8];
                v[0] = fmaxf(fmaf(ev, wes[q * 8 + 0], a0.x), 0.f);
                v[1] = fmaxf(fmaf(ev, wes[q * 8 + 1], a0.y), 0.f);
                v[2] = fmaxf(fmaf(ev, wes[q * 8 + 2], a0.z), 0.f);
                v[3] = fmaxf(fmaf(ev, wes[q * 8 + 3], a0.w), 0.f);
                v[4] = fmaxf(fmaf(ev, wes[q * 8 + 4], a1.x), 0.f);
                v[5] = fmaxf(fmaf(ev, wes[q * 8 + 5], a1.y), 0.f);
                v[6] = fmaxf(fmaf(ev, wes[q * 8 + 6], a1.z), 0.f);
                v[7] = fmaxf(fmaf(ev, wes[q * 8 + 7], a1.w), 0.f);
                uint4 hp;
                hp.x = cvt2h(v[1], v[0]);
                hp.y = cvt2h(v[3], v[2]);
                hp.z = cvt2h(v[5], v[4]);
                hp.w = cvt2h(v[7], v[6]);
                *(uint4*)(thRow + q * 16) = hp;
            }
        }
        __syncwarp();

        // ---- warp MMA: 2 m16-tiles (rows 0/16), 4 k-steps ----
        float acc[2][8][4];
#pragma unroll
        for (int mt = 0; mt < 2; mt++)
#pragma unroll
            for (int nt = 0; nt < 8; nt++)
#pragma unroll
                for (int c = 0; c < 4; c++) acc[mt][nt][c] = 0.f;

#pragma unroll
        for (int ks = 0; ks < 4; ks++) {
            uint32_t ah0[4], ah1[4];
            ldsm4(ah0, sbT + 144u * aRow + 32u * ks + aKoff);
            ldsm4(ah1, sbT + 144u * (16 + aRow) + 32u * ks + aKoff);
#pragma unroll
            for (int ntp = 0; ntp < 4; ntp++) {
                uint32_t b4[4];
                ldsm4(b4, sb + BH_OFF + bBase + 2304u * ntp + 32u * ks);
                mma16816h(acc[0][2 * ntp], ah0, b4[0], b4[1]);
                mma16816h(acc[1][2 * ntp], ah1, b4[0], b4[1]);
                mma16816h(acc[0][2 * ntp + 1], ah0, b4[2], b4[3]);
                mma16816h(acc[1][2 * ntp + 1], ah1, b4[2], b4[3]);
            }
        }
        __syncwarp();   // T reads done before Ds overlay writes

        // ---- stage D to swizzled SMEM: float4 slot = e*16 + (c4^(e&15)) ----
#pragma unroll
        for (int mt = 0; mt < 2; mt++) {
            int eb = mt * 16 + (lane >> 2);
            int h2i = lane & 1;
            int c4b = (lane & 3) >> 1;
#pragma unroll
            for (int nt = 0; nt < 8; nt++) {
                int c4 = nt * 2 + c4b;
                float2 v0 = make_float2(acc[mt][nt][0], acc[mt][nt][1]);
                float2 v1 = make_float2(acc[mt][nt][2], acc[mt][nt][3]);
                int e0 = eb, e1 = eb + 8;
                ((float2*)(Ds + (e0 * 16 + (c4 ^ (e0 & 15))) * 4))[h2i] = v0;
                ((float2*)(Ds + (e1 * 16 + (c4 ^ (e1 & 15))) * 4))[h2i] = v1;
            }
        }
        __syncwarp();

        // ---- epilogue: segmented min over 8 sorted edges, atomicMin ----
        {
            const float4* Ds4 = (const float4*)Ds;
            int ty = lane >> 3, tx = lane & 7;   // 4 edge-groups x 8 col-slices
            int cur = -2;
            float4 mA, mB;
#pragma unroll
            for (int r = 0; r < 8; r++) {
                int e = ty * 8 + r;
                int d = dstw[e];
                float4 a = Ds4[e * 16 + (tx ^ (e & 15))];
                float4 b = Ds4[e * 16 + ((8 + tx) ^ (e & 15))];
                if (r == 0 || d != cur) {
                    if (r > 0 && cur >= 0) {
                        unsigned* p0 = aggr + (size_t)cur * H + tx * 4;
                        atomicMin(p0 + 0, fenc(mA.x));
                        atomicMin(p0 + 1, fenc(mA.y));
                        atomicMin(p0 + 2, fenc(mA.z));
                        atomicMin(p0 + 3, fenc(mA.w));
                        unsigned* p1 = p0 + 32;
                        atomicMin(p1 + 0, fenc(mB.x));
                        atomicMin(p1 + 1, fenc(mB.y));
                        atomicMin(p1 + 2, fenc(mB.z));
                        atomicMin(p1 + 3, fenc(mB.w));
                    }
                    cur = d;
                    mA = a; mB = b;
                } else {
                    mA.x = fminf(mA.x, a.x); mA.y = fminf(mA.y, a.y);
                    mA.z = fminf(mA.z, a.z); mA.w = fminf(mA.w, a.w);
                    mB.x = fminf(mB.x, b.x); mB.y = fminf(mB.y, b.y);
                    mB.z = fminf(mB.z, b.z); mB.w = fminf(mB.w, b.w);
                }
            }
            if (cur >= 0) {
                unsigned* p0 = aggr + (size_t)cur * H + tx * 4;
                atomicMin(p0 + 0, fenc(mA.x));
                atomicMin(p0 + 1, fenc(mA.y));
                atomicMin(p0 + 2, fenc(mA.z));
                atomicMin(p0 + 3, fenc(mA.w));
                unsigned* p1 = p0 + 32;
                atomicMin(p1 + 0, fenc(mB.x));
                atomicMin(p1 + 1, fenc(mB.y));
                atomicMin(p1 + 2, fenc(mB.z));
                atomicMin(p1 + 3, fenc(mB.w));
            }
        }
        __syncwarp();   // Ds/dstw dead before next tile's gather writes
    }
}

// ---------------- host launch ----------------------------------------------
extern "C" void kernel_launch(void* const* d_in, const int* in_sizes, int n_in,
                              void* d_out, int out_size) {
    const float* x    = (const float*)d_in[0];
    const int*   ei   = (const int*)d_in[1];
    const float* ea   = (const float*)d_in[2];
    const float* embw = (const float*)d_in[3];
    const float* embb = (const float*)d_in[4];
    const float* mw1  = (const float*)d_in[5];
    const float* mb1  = (const float*)d_in[6];
    const float* mw2  = (const float*)d_in[7];
    const float* mb2  = (const float*)d_in[8];
    const float* uw1  = (const float*)d_in[9];
    const float* ub1  = (const float*)d_in[10];
    const float* uw2  = (const float*)d_in[11];
    const float* ub2  = (const float*)d_in[12];
    const float* fcw  = (const float*)d_in[13];
    const float* fcb  = (const float*)d_in[14];
    float* out = (float*)d_out;

    int N = in_sizes[0];
    int E = in_sizes[2];
    int L = in_sizes[6] / H;
    const int* src = ei;
    const int* dstp = ei + E;

    float* hbuf; float* Abuf; unsigned* aggr;
    int* cnt; int* cursor; int* perm;
    __half* Bh;
    cudaGetSymbolAddress((void**)&hbuf, g_h);
    cudaGetSymbolAddress((void**)&Abuf, g_A);
    cudaGetSymbolAddress((void**)&aggr, g_aggr);
    cudaGetSymbolAddress((void**)&cnt, g_cnt);
    cudaGetSymbolAddress((void**)&cursor, g_cursor);
    cudaGetSymbolAddress((void**)&perm, g_perm);
    cudaGetSymbolAddress((void**)&Bh, g_Bh);

    const size_t sm64  = (64 * 64 + 64 * 128) * 4;
    const size_t sm128 = (128 * 64 + 128 * 128 + 64) * 4;
    cudaFuncSetAttribute(edge_mma_kernel,
                         cudaFuncAttributeMaxDynamicSharedMemorySize, SMEM_EDGE);
    cudaFuncSetAttribute((node_gemm<64, false, false>),
                         cudaFuncAttributeMaxDynamicSharedMemorySize, (int)sm64);
    cudaFuncSetAttribute((node_gemm<128, true, true>),
                         cudaFuncAttributeMaxDynamicSharedMemorySize, (int)sm128);

    int nt32 = (E + 31) / 32;
    int edgeGrid = 148 * 4;
    if (edgeGrid > (nt32 + 3) / 4) edgeGrid = (nt32 + 3) / 4;
    int nodeBlocks = (N + 127) / 128;

    // embedding (+ zero cnt)
    embed_kernel<<<(N * H + 255) / 256, 256>>>(x, embw, embb, hbuf, cnt, N);
    // counting sort by dst (+ B fp16 prep, + aggr poison)
    count_kernel<<<(E + 255) / 256, 256>>>(dstp, cnt, E);
    scan_prep_kernel<<<1, 1024>>>(cnt, cursor, N, mw2, L);
    scatter_kernel<<<(E + 255) / 256, 256>>>(dstp, cursor, perm, aggr, E,
                                             N * H / 4);

    for (int l = 0; l < L; l++) {
        const float* w1 = mw1 + (size_t)l * (H + 1) * H;   // [65,64]
        // A = h @ W1[:64] + b1  (per-node hoist of per-edge msg layer 1)
        node_gemm<64, false, false><<<nodeBlocks, 128, sm64>>>(
            hbuf, nullptr, w1, mb1 + (size_t)l * H, Abuf, N, nullptr, nullptr);
        // tensor-pipe edge message + scatter-min (warp-independent tiles)
        edge_mma_kernel<<<edgeGrid, 128, SMEM_EDGE>>>(
            Abuf, src, dstp, ea, perm, w1 + (size_t)H * H,
            Bh + (size_t)l * (64 * 72), aggr, E, nt32);
        // update MLP layer 1 (fused aggr decode + b2 + re-poison)
        node_gemm<128, true, true><<<nodeBlocks, 128, sm128>>>(
            hbuf, aggr, uw1 + (size_t)l * 2 * H * H, ub1 + (size_t)l * H,
            Abuf, N, mb2 + (size_t)l * H, aggr);
        // update MLP layer 2
        node_gemm<64, false, false><<<nodeBlocks, 128, sm64>>>(
            Abuf, nullptr, uw2 + (size_t)l * H * H, ub2 + (size_t)l * H,
            hbuf, N, nullptr, nullptr);
    }

    fc_kernel<<<(N + 255) / 256, 256>>>(hbuf, fcw, fcb, out, N);
}

// round 9
// speedup vs baseline: 1.4971x; 1.2589x over previous
#include <cuda_runtime.h>
#include <cuda_bf16.h>
#include <cuda_fp16.h>
#include <cstdint>

#define H 64
#define MAXN 100000
#define MAXE 1600000
#define MAXL 8

typedef unsigned long long u64;

// ---------------- device scratch (static: no dynamic allocation allowed) ----
__device__ float         g_h[(size_t)MAXN * H];
__device__ float         g_A[(size_t)MAXN * H];
__device__ unsigned int  g_aggr[(size_t)MAXN * H];
__device__ int           g_cnt[MAXN];
__device__ int           g_cursor[MAXN];
__device__ int           g_perm[MAXE];
__device__ __half        g_Bh[MAXL * 64 * 72];  // per-layer W2^T fp16, [n][72] rows

// order-preserving float<->uint encoding for atomic min
__device__ __forceinline__ unsigned fenc(float f) {
    unsigned u = __float_as_uint(f);
    return (u & 0x80000000u) ? ~u : (u | 0x80000000u);
}
__device__ __forceinline__ float fdec(unsigned u) {
    return (u & 0x80000000u) ? __uint_as_float(u & 0x7FFFFFFFu)
                             : __uint_as_float(~u);
}

// -------- packed f32x2 helpers (node GEMMs) --------------------------------
__device__ __forceinline__ u64 pk_dup(float x) {
    u64 r;
    asm("mov.b64 %0, {%1,%1};" : "=l"(r) : "f"(x));
    return r;
}
__device__ __forceinline__ void fma2(u64& d, u64 a, u64 b) {
    asm("fma.rn.f32x2 %0, %1, %2, %3;" : "=l"(d) : "l"(a), "l"(b), "l"(d));
}
__device__ __forceinline__ void unpk(float& lo, float& hi, u64 v) {
    asm("mov.b64 {%0,%1}, %2;" : "=f"(lo), "=f"(hi) : "l"(v));
}

// -------- warp-mma plumbing (plain sm_80+ PTX) -----------------------------
__device__ __forceinline__ uint32_t smem_u32(const void* p) {
    uint32_t a;
    asm("{ .reg .u64 t; cvta.to.shared.u64 t, %1; cvt.u32.u64 %0, t; }"
        : "=r"(a) : "l"(p));
    return a;
}
__device__ __forceinline__ void ldsm4(uint32_t (&r)[4], uint32_t addr) {
    asm volatile("ldmatrix.sync.aligned.m8n8.x4.shared.b16 {%0,%1,%2,%3}, [%4];"
                 : "=r"(r[0]), "=r"(r[1]), "=r"(r[2]), "=r"(r[3]) : "r"(addr));
}
__device__ __forceinline__ void mma16816h(float (&d)[4], const uint32_t (&a)[4],
                                          uint32_t b0, uint32_t b1) {
    asm volatile(
        "mma.sync.aligned.m16n8k16.row.col.f32.f16.f16.f32 "
        "{%0,%1,%2,%3}, {%4,%5,%6,%7}, {%8,%9}, {%0,%1,%2,%3};"
        : "+f"(d[0]), "+f"(d[1]), "+f"(d[2]), "+f"(d[3])
        : "r"(a[0]), "r"(a[1]), "r"(a[2]), "r"(a[3]), "r"(b0), "r"(b1));
}
// pack f16(even)|f16(odd)<<16
__device__ __forceinline__ uint32_t cvt2h(float odd, float even) {
    uint32_t d;
    asm("cvt.rn.f16x2.f32 %0, %1, %2;" : "=r"(d) : "f"(odd), "f"(even));
    return d;
}

// ---------------- trivial elementwise kernels ------------------------------
__global__ void embed_kernel(const float* __restrict__ x,
                             const float* __restrict__ w,
                             const float* __restrict__ b,
                             float* __restrict__ h, int* __restrict__ cnt,
                             int n) {
    int i = blockIdx.x * blockDim.x + threadIdx.x;
    if (i < n) cnt[i] = 0;
    if (i < n * H) {
        int node = i >> 6, j = i & 63;
        h[i] = fmaf(x[node], w[j], b[j]);
    }
}

__global__ void count_kernel(const int* __restrict__ dst, int* cnt, int e) {
    int i = blockIdx.x * blockDim.x + threadIdx.x;
    if (i < e) atomicAdd(&cnt[dst[i]], 1);
}

// prefix scan of cnt + precompute per-layer fp16 B = W2^T (stride 72)
__global__ void scan_prep_kernel(const int* __restrict__ cnt,
                                 int* __restrict__ cursor, int n,
                                 const float* __restrict__ mw2, int L) {
    int tid = threadIdx.x;
    int total = L * H * H;
    for (int i = tid; i < total; i += 1024) {
        int l = i >> 12, rem = i & 4095;
        int nn = rem >> 6, k = rem & 63;
        float w = mw2[(size_t)l * 4096 + k * 64 + nn];
        g_Bh[(size_t)l * (64 * 72) + nn * 72 + k] = __float2half_rn(w);
    }
    __shared__ int s[1024];
    int chunk = (n + 1023) >> 10;
    int lo = tid * chunk;
    int hi = min(lo + chunk, n);
    int sum = 0;
    for (int i = lo; i < hi; i++) sum += cnt[i];
    s[tid] = sum;
    __syncthreads();
    for (int off = 1; off < 1024; off <<= 1) {
        int v = (tid >= off) ? s[tid - off] : 0;
        __syncthreads();
        s[tid] += v;
        __syncthreads();
    }
    int run = s[tid] - sum;
    for (int i = lo; i < hi; i++) { cursor[i] = run; run += cnt[i]; }
}

// scatter (build perm) + init aggr to encoded +inf
__global__ void scatter_kernel(const int* __restrict__ dst, int* cursor,
                               int* perm, unsigned* __restrict__ aggr,
                               int e, int nH4) {
    int i = blockIdx.x * blockDim.x + threadIdx.x;
    if (i < e) {
        int p = atomicAdd(&cursor[dst[i]], 1);
        perm[p] = i;
    }
    uint4 f = make_uint4(~0u, ~0u, ~0u, ~0u);
    for (int j = i; j < nH4; j += gridDim.x * blockDim.x)
        ((uint4*)aggr)[j] = f;
}

__global__ void fc_kernel(const float* __restrict__ h,
                          const float* __restrict__ fcw,
                          const float* __restrict__ fcb,
                          float* __restrict__ out, int n) {
    int i = blockIdx.x * blockDim.x + threadIdx.x;
    if (i >= n) return;
    const float4* h4 = (const float4*)(h + (size_t)i * H);
    const float4* w4 = (const float4*)fcw;
    float s = 0.f;
#pragma unroll
    for (int q = 0; q < 16; q++) {
        float4 a = h4[q], w = w4[q];
        s += a.x * w.x + a.y * w.y + a.z * w.z + a.w * w.w;
    }
    out[i] = s + fcb[0];
}

// -------- node GEMM (fp32 f32x2 path; DECODE fuses aggr finalize) ----------
template <int K>
__device__ __forceinline__ void gemm_body(const float* Xs, const float* Ws,
                                          int ty, int tx, u64 acc2[8][4]) {
    const float4* Xs4 = (const float4*)Xs;
#pragma unroll 4
    for (int k = 0; k < K; k++) {
        float4 a0 = Xs4[k * 32 + ty * 2];
        float4 a1 = Xs4[k * 32 + ty * 2 + 1];
        const ulonglong2* Wp = (const ulonglong2*)(Ws + k * 64 + tx * 8);
        ulonglong2 w01 = Wp[0];
        ulonglong2 w23 = Wp[1];
        u64 aa[8] = {pk_dup(a0.x), pk_dup(a0.y), pk_dup(a0.z), pk_dup(a0.w),
                     pk_dup(a1.x), pk_dup(a1.y), pk_dup(a1.z), pk_dup(a1.w)};
#pragma unroll
        for (int r = 0; r < 8; r++) {
            fma2(acc2[r][0], aa[r], w01.x);
            fma2(acc2[r][1], aa[r], w01.y);
            fma2(acc2[r][2], aa[r], w23.x);
            fma2(acc2[r][3], aa[r], w23.y);
        }
    }
}

template <int K, bool RELU, bool DECODE>
__global__ void __launch_bounds__(128)
node_gemm(const float* __restrict__ X1, const void* __restrict__ X2p,
          const float* __restrict__ W, const float* __restrict__ bias,
          float* __restrict__ C, int Nn,
          const float* __restrict__ b2g, unsigned* __restrict__ aggrw) {
    extern __shared__ float sm[];
    float* Ws = sm;
    float* Xs = sm + K * 64;
    float* b2s = sm + K * 64 + K * 128;   // 64 floats (DECODE only)
    int tid = threadIdx.x;
    int n0 = blockIdx.x * 128;
    {
        const float4* W4 = (const float4*)W;
        float4* Ws4 = (float4*)Ws;
#pragma unroll
        for (int i = 0; i < K / 8; i++) Ws4[tid + i * 128] = W4[tid + i * 128];
    }
    int n = min(n0 + tid, Nn - 1);
    {
        const float4* X14 = (const float4*)(X1 + (size_t)n * H);
#pragma unroll
        for (int q = 0; q < 16; q++) {
            float4 v = X14[q];
            Xs[(4 * q + 0) * 128 + tid] = v.x;
            Xs[(4 * q + 1) * 128 + tid] = v.y;
            Xs[(4 * q + 2) * 128 + tid] = v.z;
            Xs[(4 * q + 3) * 128 + tid] = v.w;
        }
    }
    if (DECODE) {
        if (tid < 64) b2s[tid] = b2g[tid];
        __syncthreads();
    }
    if (K == 128) {
        if (DECODE) {
            const uint4* X24 = (const uint4*)((const unsigned*)X2p +
                                              (size_t)n * H);
#pragma unroll
            for (int q = 0; q < 16; q++) {
                uint4 u = X24[q];
                float4 v;
                v.x = (u.x >= 0xFF800000u) ? 0.f : (fdec(u.x) + b2s[4 * q + 0]);
                v.y = (u.y >= 0xFF800000u) ? 0.f : (fdec(u.y) + b2s[4 * q + 1]);
                v.z = (u.z >= 0xFF800000u) ? 0.f : (fdec(u.z) + b2s[4 * q + 2]);
                v.w = (u.w >= 0xFF800000u) ? 0.f : (fdec(u.w) + b2s[4 * q + 3]);
                Xs[(64 + 4 * q + 0) * 128 + tid] = v.x;
                Xs[(64 + 4 * q + 1) * 128 + tid] = v.y;
                Xs[(64 + 4 * q + 2) * 128 + tid] = v.z;
                Xs[(64 + 4 * q + 3) * 128 + tid] = v.w;
            }
            // re-poison aggr for next layer (owner thread only; safe at tail)
            if (n0 + tid < Nn) {
                uint4 p = make_uint4(~0u, ~0u, ~0u, ~0u);
                uint4* A4 = (uint4*)(aggrw + (size_t)n * H);
#pragma unroll
                for (int q = 0; q < 16; q++) A4[q] = p;
            }
        } else {
            const float4* X24 = (const float4*)((const float*)X2p +
                                                (size_t)n * H);
#pragma unroll
            for (int q = 0; q < 16; q++) {
                float4 v = X24[q];
                Xs[(64 + 4 * q + 0) * 128 + tid] = v.x;
                Xs[(64 + 4 * q + 1) * 128 + tid] = v.y;
                Xs[(64 + 4 * q + 2) * 128 + tid] = v.z;
                Xs[(64 + 4 * q + 3) * 128 + tid] = v.w;
            }
        }
    }
    __syncthreads();
    int ty = tid >> 3, tx = tid & 7;
    u64 acc2[8][4];
#pragma unroll
    for (int r = 0; r < 8; r++)
#pragma unroll
        for (int c = 0; c < 4; c++) acc2[r][c] = 0ull;
    gemm_body<K>(Xs, Ws, ty, tx, acc2);
    float bb[8];
#pragma unroll
    for (int c = 0; c < 8; c++) bb[c] = bias[tx * 8 + c];
#pragma unroll
    for (int r = 0; r < 8; r++) {
        int nr = n0 + ty * 8 + r;
        if (nr < Nn) {
            float o[8];
            unpk(o[0], o[1], acc2[r][0]);
            unpk(o[2], o[3], acc2[r][1]);
            unpk(o[4], o[5], acc2[r][2]);
            unpk(o[6], o[7], acc2[r][3]);
            float4 o0, o1;
            o0.x = o[0] + bb[0]; o0.y = o[1] + bb[1];
            o0.z = o[2] + bb[2]; o0.w = o[3] + bb[3];
            o1.x = o[4] + bb[4]; o1.y = o[5] + bb[5];
            o1.z = o[6] + bb[6]; o1.w = o[7] + bb[7];
            if (RELU) {
                o0.x = fmaxf(o0.x, 0.f); o0.y = fmaxf(o0.y, 0.f);
                o0.z = fmaxf(o0.z, 0.f); o0.w = fmaxf(o0.w, 0.f);
                o1.x = fmaxf(o1.x, 0.f); o1.y = fmaxf(o1.y, 0.f);
                o1.z = fmaxf(o1.z, 0.f); o1.w = fmaxf(o1.w, 0.f);
            }
            float4* C4 = (float4*)(C + (size_t)nr * H);
            C4[tx * 2] = o0;
            C4[tx * 2 + 1] = o1;
        }
    }
}

// ---------------- HMMA edge kernel (persistent, warp tiles, coalesced) -----
// Each WARP owns a 32-edge tile in a private 8KB smem region.
// Gather is COALESCED: each LDG.128 covers 2 A-rows x 16 consecutive chunks
// (4 cache lines/instr = 64 L1tex wavefronts/tile vs 512 for row-per-thread).
// Per-row src/ev broadcast from registers via shfl. Element arithmetic is
// unchanged -> bitwise-identical output to R7/R8.
#define TW_STRIDE 8192        // per-warp union: T (32x144=4608B) / Ds (8192B)
#define BH_OFF   32768        // 64 x 72 f16 = 9216 B (CTA-shared)
#define WES_OFF  41984        // 64 f32
#define DST_OFF  42240        // 4 warps x 32 int
#define SMEM_EDGE 42752

__global__ void __launch_bounds__(128, 4)
edge_mma_kernel(const float* __restrict__ Ag, const int* __restrict__ src,
                const int* __restrict__ dstp, const float* __restrict__ ea,
                const int* __restrict__ perm, const float* __restrict__ weg,
                const __half* __restrict__ Bh_g,
                unsigned* __restrict__ aggr, int E, int nt32) {
    extern __shared__ char smc[];
    uint32_t sb = smem_u32(smc);
    int tid = threadIdx.x;
    int lane = tid & 31;
    int wid = tid >> 5;

    // one-time: copy B (576 uint4) + we into smem (CTA-shared, read-only)
    {
        const uint4* s4 = (const uint4*)Bh_g;
        uint4* d4 = (uint4*)(smc + BH_OFF);
        for (int i = tid; i < 576; i += 128) d4[i] = s4[i];
        if (tid < 64) ((float*)(smc + WES_OFF))[tid] = weg[tid];
    }
    __syncthreads();

    const float* wes = (const float*)(smc + WES_OFF);
    char* Tw = smc + wid * TW_STRIDE;
    uint32_t sbT = sb + wid * TW_STRIDE;
    float* Ds = (float*)Tw;                       // overlay after mma reads
    int* dstw = (int*)(smc + DST_OFF + wid * 128);

    // ldmatrix lane-address components
    uint32_t aRow = (lane & 7) + 8u * ((lane >> 3) & 1);
    uint32_t aKoff = 16u * (lane >> 4);
    uint32_t bBase = 144u * (8u * ((lane >> 4) & 1) + (lane & 7)) +
                     16u * ((lane >> 3) & 1);

    // cooperative-gather lane roles (fixed across tiles)
    int gc = lane & 15;          // chunk index within row (float4 units)
    int ghalf = lane >> 4;       // which of the 2 rows per iteration
    float4 wch = ((const float4*)wes)[gc];   // this lane's we chunk

    for (int t = blockIdx.x * 4 + wid; t < nt32; t += gridDim.x * 4) {
        // ---- coalesced gather + relu + fp16 -> T rows (144B stride) ----
        {
            int slot = t * 32 + lane;
            int eidx = perm[min(slot, E - 1)];
            int s = src[eidx];
            float ev = ea[eidx];
            dstw[lane] = (slot < E) ? dstp[eidx] : -1;
#pragma unroll
            for (int rp = 0; rp < 16; rp++) {
                int r = rp * 2 + ghalf;
                int srow = __shfl_sync(0xFFFFFFFFu, s, r);
                float evr = __shfl_sync(0xFFFFFFFFu, ev, r);
                float4 a = ((const float4*)(Ag + (size_t)srow * H))[gc];
                float v0 = fmaxf(fmaf(evr, wch.x, a.x), 0.f);
                float v1 = fmaxf(fmaf(evr, wch.y, a.y), 0.f);
                float v2 = fmaxf(fmaf(evr, wch.z, a.z), 0.f);
                float v3 = fmaxf(fmaf(evr, wch.w, a.w), 0.f);
                uint2 hp;
                hp.x = cvt2h(v1, v0);
                hp.y = cvt2h(v3, v2);
                *(uint2*)(Tw + r * 144 + gc * 8) = hp;
            }
        }
        __syncwarp();

        // ---- warp MMA: 2 m16-tiles (rows 0/16), 4 k-steps ----
        float acc[2][8][4];
#pragma unroll
        for (int mt = 0; mt < 2; mt++)
#pragma unroll
            for (int nt = 0; nt < 8; nt++)
#pragma unroll
                for (int c = 0; c < 4; c++) acc[mt][nt][c] = 0.f;

#pragma unroll
        for (int ks = 0; ks < 4; ks++) {
            uint32_t ah0[4], ah1[4];
            ldsm4(ah0, sbT + 144u * aRow + 32u * ks + aKoff);
            ldsm4(ah1, sbT + 144u * (16 + aRow) + 32u * ks + aKoff);
#pragma unroll
            for (int ntp = 0; ntp < 4; ntp++) {
                uint32_t b4[4];
                ldsm4(b4, sb + BH_OFF + bBase + 2304u * ntp + 32u * ks);
                mma16816h(acc[0][2 * ntp], ah0, b4[0], b4[1]);
                mma16816h(acc[1][2 * ntp], ah1, b4[0], b4[1]);
                mma16816h(acc[0][2 * ntp + 1], ah0, b4[2], b4[3]);
                mma16816h(acc[1][2 * ntp + 1], ah1, b4[2], b4[3]);
            }
        }
        __syncwarp();   // T reads done before Ds overlay writes

        // ---- stage D to swizzled SMEM: float4 slot = e*16 + (c4^(e&15)) ----
#pragma unroll
        for (int mt = 0; mt < 2; mt++) {
            int eb = mt * 16 + (lane >> 2);
            int h2i = lane & 1;
            int c4b = (lane & 3) >> 1;
#pragma unroll
            for (int nt = 0; nt < 8; nt++) {
                int c4 = nt * 2 + c4b;
                float2 v0 = make_float2(acc[mt][nt][0], acc[mt][nt][1]);
                float2 v1 = make_float2(acc[mt][nt][2], acc[mt][nt][3]);
                int e0 = eb, e1 = eb + 8;
                ((float2*)(Ds + (e0 * 16 + (c4 ^ (e0 & 15))) * 4))[h2i] = v0;
                ((float2*)(Ds + (e1 * 16 + (c4 ^ (e1 & 15))) * 4))[h2i] = v1;
            }
        }
        __syncwarp();

        // ---- epilogue: segmented min over 8 sorted edges, atomicMin ----
        {
            const float4* Ds4 = (const float4*)Ds;
            int ty = lane >> 3, tx = lane & 7;   // 4 edge-groups x 8 col-slices
            int cur = -2;
            float4 mA, mB;
#pragma unroll
            for (int r = 0; r < 8; r++) {
                int e = ty * 8 + r;
                int d = dstw[e];
                float4 a = Ds4[e * 16 + (tx ^ (e & 15))];
                float4 b = Ds4[e * 16 + ((8 + tx) ^ (e & 15))];
                if (r == 0 || d != cur) {
                    if (r > 0 && cur >= 0) {
                        unsigned* p0 = aggr + (size_t)cur * H + tx * 4;
                        atomicMin(p0 + 0, fenc(mA.x));
                        atomicMin(p0 + 1, fenc(mA.y));
                        atomicMin(p0 + 2, fenc(mA.z));
                        atomicMin(p0 + 3, fenc(mA.w));
                        unsigned* p1 = p0 + 32;
                        atomicMin(p1 + 0, fenc(mB.x));
                        atomicMin(p1 + 1, fenc(mB.y));
                        atomicMin(p1 + 2, fenc(mB.z));
                        atomicMin(p1 + 3, fenc(mB.w));
                    }
                    cur = d;
                    mA = a; mB = b;
                } else {
                    mA.x = fminf(mA.x, a.x); mA.y = fminf(mA.y, a.y);
                    mA.z = fminf(mA.z, a.z); mA.w = fminf(mA.w, a.w);
                    mB.x = fminf(mB.x, b.x); mB.y = fminf(mB.y, b.y);
                    mB.z = fminf(mB.z, b.z); mB.w = fminf(mB.w, b.w);
                }
            }
            if (cur >= 0) {
                unsigned* p0 = aggr + (size_t)cur * H + tx * 4;
                atomicMin(p0 + 0, fenc(mA.x));
                atomicMin(p0 + 1, fenc(mA.y));
                atomicMin(p0 + 2, fenc(mA.z));
                atomicMin(p0 + 3, fenc(mA.w));
                unsigned* p1 = p0 + 32;
                atomicMin(p1 + 0, fenc(mB.x));
                atomicMin(p1 + 1, fenc(mB.y));
                atomicMin(p1 + 2, fenc(mB.z));
                atomicMin(p1 + 3, fenc(mB.w));
            }
        }
        __syncwarp();   // Ds/dstw dead before next tile's gather writes
    }
}

// ---------------- host launch ----------------------------------------------
extern "C" void kernel_launch(void* const* d_in, const int* in_sizes, int n_in,
                              void* d_out, int out_size) {
    const float* x    = (const float*)d_in[0];
    const int*   ei   = (const int*)d_in[1];
    const float* ea   = (const float*)d_in[2];
    const float* embw = (const float*)d_in[3];
    const float* embb = (const float*)d_in[4];
    const float* mw1  = (const float*)d_in[5];
    const float* mb1  = (const float*)d_in[6];
    const float* mw2  = (const float*)d_in[7];
    const float* mb2  = (const float*)d_in[8];
    const float* uw1  = (const float*)d_in[9];
    const float* ub1  = (const float*)d_in[10];
    const float* uw2  = (const float*)d_in[11];
    const float* ub2  = (const float*)d_in[12];
    const float* fcw  = (const float*)d_in[13];
    const float* fcb  = (const float*)d_in[14];
    float* out = (float*)d_out;

    int N = in_sizes[0];
    int E = in_sizes[2];
    int L = in_sizes[6] / H;
    const int* src = ei;
    const int* dstp = ei + E;

    float* hbuf; float* Abuf; unsigned* aggr;
    int* cnt; int* cursor; int* perm;
    __half* Bh;
    cudaGetSymbolAddress((void**)&hbuf, g_h);
    cudaGetSymbolAddress((void**)&Abuf, g_A);
    cudaGetSymbolAddress((void**)&aggr, g_aggr);
    cudaGetSymbolAddress((void**)&cnt, g_cnt);
    cudaGetSymbolAddress((void**)&cursor, g_cursor);
    cudaGetSymbolAddress((void**)&perm, g_perm);
    cudaGetSymbolAddress((void**)&Bh, g_Bh);

    const size_t sm64  = (64 * 64 + 64 * 128) * 4;
    const size_t sm128 = (128 * 64 + 128 * 128 + 64) * 4;
    cudaFuncSetAttribute(edge_mma_kernel,
                         cudaFuncAttributeMaxDynamicSharedMemorySize, SMEM_EDGE);
    cudaFuncSetAttribute((node_gemm<64, false, false>),
                         cudaFuncAttributeMaxDynamicSharedMemorySize, (int)sm64);
    cudaFuncSetAttribute((node_gemm<128, true, true>),
                         cudaFuncAttributeMaxDynamicSharedMemorySize, (int)sm128);

    int nt32 = (E + 31) / 32;
    int edgeGrid = 148 * 4;
    if (edgeGrid > (nt32 + 3) / 4) edgeGrid = (nt32 + 3) / 4;
    int nodeBlocks = (N + 127) / 128;

    // embedding (+ zero cnt)
    embed_kernel<<<(N * H + 255) / 256, 256>>>(x, embw, embb, hbuf, cnt, N);
    // counting sort by dst (+ B fp16 prep, + aggr poison)
    count_kernel<<<(E + 255) / 256, 256>>>(dstp, cnt, E);
    scan_prep_kernel<<<1, 1024>>>(cnt, cursor, N, mw2, L);
    scatter_kernel<<<(E + 255) / 256, 256>>>(dstp, cursor, perm, aggr, E,
                                             N * H / 4);

    for (int l = 0; l < L; l++) {
        const float* w1 = mw1 + (size_t)l * (H + 1) * H;   // [65,64]
        // A = h @ W1[:64] + b1  (per-node hoist of per-edge msg layer 1)
        node_gemm<64, false, false><<<nodeBlocks, 128, sm64>>>(
            hbuf, nullptr, w1, mb1 + (size_t)l * H, Abuf, N, nullptr, nullptr);
        // tensor-pipe edge message + scatter-min (coalesced gather)
        edge_mma_kernel<<<edgeGrid, 128, SMEM_EDGE>>>(
            Abuf, src, dstp, ea, perm, w1 + (size_t)H * H,
            Bh + (size_t)l * (64 * 72), aggr, E, nt32);
        // update MLP layer 1 (fused aggr decode + b2 + re-poison)
        node_gemm<128, true, true><<<nodeBlocks, 128, sm128>>>(
            hbuf, aggr, uw1 + (size_t)l * 2 * H * H, ub1 + (size_t)l * H,
            Abuf, N, mb2 + (size_t)l * H, aggr);
        // update MLP layer 2
        node_gemm<64, false, false><<<nodeBlocks, 128, sm64>>>(
            Abuf, nullptr, uw2 + (size_t)l * H * H, ub2 + (size_t)l * H,
            hbuf, N, nullptr, nullptr);
    }

    fc_kernel<<<(N + 255) / 256, 256>>>(hbuf, fcw, fcb, out, N);
}

// round 10
// speedup vs baseline: 1.7949x; 1.1989x over previous
#include <cuda_runtime.h>
#include <cuda_bf16.h>
#include <cuda_fp16.h>
#include <cstdint>

#define H 64
#define MAXN 100000
#define MAXE 1600000
#define MAXL 8

typedef unsigned long long u64;

// ---------------- device scratch (static: no dynamic allocation allowed) ----
__device__ float         g_h[(size_t)MAXN * H];
__device__ float         g_A[(size_t)MAXN * H];
__device__ unsigned int  g_aggr[(size_t)MAXN * H];
__device__ int           g_cnt[MAXN];
__device__ int           g_cursor[MAXN];
__device__ int           g_perm[MAXE];
__device__ __half        g_Bh[MAXL * 64 * 72];        // edge W2^T fp16 [n][72]
__device__ __half        g_NBh[MAXL * 4 * 64 * 72];   // node weights hi [l][g][n][72]
__device__ __half        g_NBl[MAXL * 4 * 64 * 72];   // node weights lo

// order-preserving float<->uint encoding for atomic min
__device__ __forceinline__ unsigned fenc(float f) {
    unsigned u = __float_as_uint(f);
    return (u & 0x80000000u) ? ~u : (u | 0x80000000u);
}
__device__ __forceinline__ float fdec(unsigned u) {
    return (u & 0x80000000u) ? __uint_as_float(u & 0x7FFFFFFFu)
                             : __uint_as_float(~u);
}

// -------- warp-mma plumbing (plain sm_80+ PTX) -----------------------------
__device__ __forceinline__ uint32_t smem_u32(const void* p) {
    uint32_t a;
    asm("{ .reg .u64 t; cvta.to.shared.u64 t, %1; cvt.u32.u64 %0, t; }"
        : "=r"(a) : "l"(p));
    return a;
}
__device__ __forceinline__ void ldsm4(uint32_t (&r)[4], uint32_t addr) {
    asm volatile("ldmatrix.sync.aligned.m8n8.x4.shared.b16 {%0,%1,%2,%3}, [%4];"
                 : "=r"(r[0]), "=r"(r[1]), "=r"(r[2]), "=r"(r[3]) : "r"(addr));
}
__device__ __forceinline__ void mma16816h(float (&d)[4], const uint32_t (&a)[4],
                                          uint32_t b0, uint32_t b1) {
    asm volatile(
        "mma.sync.aligned.m16n8k16.row.col.f32.f16.f16.f32 "
        "{%0,%1,%2,%3}, {%4,%5,%6,%7}, {%8,%9}, {%0,%1,%2,%3};"
        : "+f"(d[0]), "+f"(d[1]), "+f"(d[2]), "+f"(d[3])
        : "r"(a[0]), "r"(a[1]), "r"(a[2]), "r"(a[3]), "r"(b0), "r"(b1));
}
// pack f16(even)|f16(odd)<<16
__device__ __forceinline__ uint32_t cvt2h(float odd, float even) {
    uint32_t d;
    asm("cvt.rn.f16x2.f32 %0, %1, %2;" : "=r"(d) : "f"(odd), "f"(even));
    return d;
}
__device__ __forceinline__ float2 h22f2(uint32_t h) {
    __half2 hh = *(__half2*)&h;
    return __half22float2(hh);
}

// ---------------- trivial elementwise kernels ------------------------------
__global__ void embed_kernel(const float* __restrict__ x,
                             const float* __restrict__ w,
                             const float* __restrict__ b,
                             float* __restrict__ h, int* __restrict__ cnt,
                             int n) {
    int i = blockIdx.x * blockDim.x + threadIdx.x;
    if (i < n) cnt[i] = 0;
    if (i < n * H) {
        int node = i >> 6, j = i & 63;
        h[i] = fmaf(x[node], w[j], b[j]);
    }
}

__global__ void count_kernel(const int* __restrict__ dst, int* cnt, int e) {
    int i = blockIdx.x * blockDim.x + threadIdx.x;
    if (i < e) atomicAdd(&cnt[dst[i]], 1);
}

// prefix scan of cnt + precompute fp16 weight tiles:
//  g_Bh: edge W2^T [n][72] (single fp16)
//  g_NBh/g_NBl: node-GEMM B = W^T per layer, 4 chunk-slots of [64][72] hi/lo:
//   slot 0: msg W1[:64]^T  slot 1,2: upd W1^T (K chunks)  slot 3: upd W2^T
__global__ void scan_prep_kernel(const int* __restrict__ cnt,
                                 int* __restrict__ cursor, int n,
                                 const float* __restrict__ mw2,
                                 const float* __restrict__ mw1,
                                 const float* __restrict__ uw1,
                                 const float* __restrict__ uw2, int L) {
    int tid = threadIdx.x;
    int total = L * H * H;
    for (int i = tid; i < total; i += 1024) {
        int l = i >> 12, rem = i & 4095;
        int nn = rem >> 6, k = rem & 63;
        float w = mw2[(size_t)l * 4096 + k * 64 + nn];
        g_Bh[(size_t)l * (64 * 72) + nn * 72 + k] = __float2half_rn(w);
    }
    int totN = L * 4 * 4096;
    for (int i = tid; i < totN; i += 1024) {
        int l = i >> 14;
        int g = (i >> 12) & 3;
        int rem = i & 4095;
        int nn = rem >> 6, k = rem & 63;
        float w;
        if (g == 0)      w = mw1[(size_t)l * 65 * 64 + k * 64 + nn];
        else if (g <= 2) w = uw1[(size_t)l * 128 * 64 + ((g - 1) * 64 + k) * 64 + nn];
        else             w = uw2[(size_t)l * 64 * 64 + k * 64 + nn];
        __half hi = __float2half_rn(w);
        __half lo = __float2half_rn(w - __half2float(hi));
        size_t off = (size_t)(l * 4 + g) * 4608 + nn * 72 + k;
        g_NBh[off] = hi;
        g_NBl[off] = lo;
    }
    __shared__ int s[1024];
    int chunk = (n + 1023) >> 10;
    int lo = tid * chunk;
    int hi = min(lo + chunk, n);
    int sum = 0;
    for (int i = lo; i < hi; i++) sum += cnt[i];
    s[tid] = sum;
    __syncthreads();
    for (int off = 1; off < 1024; off <<= 1) {
        int v = (tid >= off) ? s[tid - off] : 0;
        __syncthreads();
        s[tid] += v;
        __syncthreads();
    }
    int run = s[tid] - sum;
    for (int i = lo; i < hi; i++) { cursor[i] = run; run += cnt[i]; }
}

// scatter (build perm) + init aggr to encoded +inf
__global__ void scatter_kernel(const int* __restrict__ dst, int* cursor,
                               int* perm, unsigned* __restrict__ aggr,
                               int e, int nH4) {
    int i = blockIdx.x * blockDim.x + threadIdx.x;
    if (i < e) {
        int p = atomicAdd(&cursor[dst[i]], 1);
        perm[p] = i;
    }
    uint4 f = make_uint4(~0u, ~0u, ~0u, ~0u);
    for (int j = i; j < nH4; j += gridDim.x * blockDim.x)
        ((uint4*)aggr)[j] = f;
}

__global__ void fc_kernel(const float* __restrict__ h,
                          const float* __restrict__ fcw,
                          const float* __restrict__ fcb,
                          float* __restrict__ out, int n) {
    int i = blockIdx.x * blockDim.x + threadIdx.x;
    if (i >= n) return;
    const float4* h4 = (const float4*)(h + (size_t)i * H);
    const float4* w4 = (const float4*)fcw;
    float s = 0.f;
#pragma unroll
    for (int q = 0; q < 16; q++) {
        float4 a = h4[q], w = w4[q];
        s += a.x * w.x + a.y * w.y + a.z * w.z + a.w * w.w;
    }
    out[i] = s + fcb[0];
}

// ---------------- node GEMM via HMMA, 3-term fp16 split --------------------
// C[N,64] = act( X @ W + bias ), K = NC*64, warp-tile = 32 consecutive rows.
// X split X = Xh + Xl (exact fp16 pair), W pre-split Wh + Wl:
// D = XhWh + XlWh + XhWl (residual XlWl ~ 2^-22, negligible).
// DECODE: chunk 1 input is encoded-min aggr -> decode + b2, re-poison.
// smem: T hi/lo per warp (9216B x4) | B chunks (NC*18432) | bias(256)+b2(256)
#define NM_B_OFF 36864

template <int NC, bool RELU, bool DECODE>
__global__ void __launch_bounds__(128, NC == 1 ? 4 : 3)
node_mma(const float* __restrict__ X1, const unsigned* __restrict__ X2,
         const __half* __restrict__ NBh_g, const __half* __restrict__ NBl_g,
         const float* __restrict__ bias, const float* __restrict__ b2g,
         unsigned* __restrict__ aggrw, float* __restrict__ C, int Nn) {
    extern __shared__ char smc[];
    uint32_t sb = smem_u32(smc);
    int tid = threadIdx.x;
    int lane = tid & 31;
    int wid = tid >> 5;
    const int BIAS_OFF = NM_B_OFF + NC * 18432;

    // load B chunks (hi at +0, lo at +9216 within each 18432B chunk) + bias/b2
    {
        const uint4* sh = (const uint4*)NBh_g;
        const uint4* sl = (const uint4*)NBl_g;
        for (int i = tid; i < NC * 576; i += 128) {
            int c = i / 576, j = i - c * 576;
            ((uint4*)(smc + NM_B_OFF + c * 18432))[j] = sh[i];
            ((uint4*)(smc + NM_B_OFF + c * 18432 + 9216))[j] = sl[i];
        }
        if (tid < 64) ((float*)(smc + BIAS_OFF))[tid] = bias[tid];
        if (DECODE && tid >= 64 && tid < 128)
            ((float*)(smc + BIAS_OFF))[tid] = b2g[tid - 64];
    }
    __syncthreads();

    int n0 = blockIdx.x * 128;
    int m0base = n0 + wid * 32;
    char* Tw = smc + wid * 9216;                 // Th +0, Tl +4608
    uint32_t sbT = sb + wid * 9216;

    // ldmatrix lane-address components (stride-144 rows, shared with edge)
    uint32_t aRow = (lane & 7) + 8u * ((lane >> 3) & 1);
    uint32_t aKoff = 16u * (lane >> 4);
    uint32_t bBase = 144u * (8u * ((lane >> 4) & 1) + (lane & 7)) +
                     16u * ((lane >> 3) & 1);
    int gc = lane & 15, gh = lane >> 4;

    float acc[2][8][4];
#pragma unroll
    for (int mt = 0; mt < 2; mt++)
#pragma unroll
        for (int nt = 0; nt < 8; nt++)
#pragma unroll
            for (int c = 0; c < 4; c++) acc[mt][nt][c] = 0.f;

#pragma unroll
    for (int c = 0; c < NC; c++) {
        // ---- fill T hi/lo for this K-chunk (coalesced: rows consecutive) --
#pragma unroll 4
        for (int rp = 0; rp < 16; rp++) {
            int r = rp * 2 + gh;
            int rowu = m0base + r;
            int row = min(rowu, Nn - 1);
            float v0, v1, v2, v3;
            if (DECODE && c == 1) {
                uint4 u = ((const uint4*)(X2 + (size_t)row * H))[gc];
                float4 b2v = ((const float4*)(smc + BIAS_OFF + 256))[gc];
                v0 = (u.x >= 0xFF800000u) ? 0.f : (fdec(u.x) + b2v.x);
                v1 = (u.y >= 0xFF800000u) ? 0.f : (fdec(u.y) + b2v.y);
                v2 = (u.z >= 0xFF800000u) ? 0.f : (fdec(u.z) + b2v.z);
                v3 = (u.w >= 0xFF800000u) ? 0.f : (fdec(u.w) + b2v.w);
                if (rowu < Nn)
                    ((uint4*)(aggrw + (size_t)row * H))[gc] =
                        make_uint4(~0u, ~0u, ~0u, ~0u);
            } else {
                float4 a = ((const float4*)(X1 + (size_t)row * H))[gc];
                v0 = a.x; v1 = a.y; v2 = a.z; v3 = a.w;
            }
            uint32_t h01 = cvt2h(v1, v0);
            float2 bk0 = h22f2(h01);
            uint32_t l01 = cvt2h(v1 - bk0.y, v0 - bk0.x);
            uint32_t h23 = cvt2h(v3, v2);
            float2 bk1 = h22f2(h23);
            uint32_t l23 = cvt2h(v3 - bk1.y, v2 - bk1.x);
            *(uint2*)(Tw + r * 144 + gc * 8) = make_uint2(h01, h23);
            *(uint2*)(Tw + 4608 + r * 144 + gc * 8) = make_uint2(l01, l23);
        }
        __syncwarp();

        // ---- MMA this chunk: 3 terms x 4 k-steps x 8 n-tiles x 2 m-tiles --
        uint32_t Bc = sb + NM_B_OFF + c * 18432;
#pragma unroll
        for (int ks = 0; ks < 4; ks++) {
            uint32_t ah0[4], ah1[4], al0[4], al1[4];
            ldsm4(ah0, sbT + 144u * aRow + 32u * ks + aKoff);
            ldsm4(ah1, sbT + 144u * (16 + aRow) + 32u * ks + aKoff);
            ldsm4(al0, sbT + 4608u + 144u * aRow + 32u * ks + aKoff);
            ldsm4(al1, sbT + 4608u + 144u * (16 + aRow) + 32u * ks + aKoff);
#pragma unroll
            for (int ntp = 0; ntp < 4; ntp++) {
                uint32_t bh[4], bl[4];
                ldsm4(bh, Bc + bBase + 2304u * ntp + 32u * ks);
                ldsm4(bl, Bc + 9216u + bBase + 2304u * ntp + 32u * ks);
                mma16816h(acc[0][2 * ntp], ah0, bh[0], bh[1]);
                mma16816h(acc[1][2 * ntp], ah1, bh[0], bh[1]);
                mma16816h(acc[0][2 * ntp + 1], ah0, bh[2], bh[3]);
                mma16816h(acc[1][2 * ntp + 1], ah1, bh[2], bh[3]);
                mma16816h(acc[0][2 * ntp], al0, bh[0], bh[1]);
                mma16816h(acc[1][2 * ntp], al1, bh[0], bh[1]);
                mma16816h(acc[0][2 * ntp + 1], al0, bh[2], bh[3]);
                mma16816h(acc[1][2 * ntp + 1], al1, bh[2], bh[3]);
                mma16816h(acc[0][2 * ntp], ah0, bl[0], bl[1]);
                mma16816h(acc[1][2 * ntp], ah1, bl[0], bl[1]);
                mma16816h(acc[0][2 * ntp + 1], ah0, bl[2], bl[3]);
                mma16816h(acc[1][2 * ntp + 1], ah1, bl[2], bl[3]);
            }
        }
        __syncwarp();   // T reads in regs before next chunk overwrites
    }

    // ---- epilogue: bias (+relu) and direct global store ----
    const float* bs = (const float*)(smc + BIAS_OFF);
#pragma unroll
    for (int mt = 0; mt < 2; mt++) {
        int row = m0base + mt * 16 + (lane >> 2);
        int colb = (lane & 3) * 2;
#pragma unroll
        for (int nt = 0; nt < 8; nt++) {
            int cc = nt * 8 + colb;
            float b0 = bs[cc], b1 = bs[cc + 1];
            float2 v0 = make_float2(acc[mt][nt][0] + b0, acc[mt][nt][1] + b1);
            float2 v1 = make_float2(acc[mt][nt][2] + b0, acc[mt][nt][3] + b1);
            if (RELU) {
                v0.x = fmaxf(v0.x, 0.f); v0.y = fmaxf(v0.y, 0.f);
                v1.x = fmaxf(v1.x, 0.f); v1.y = fmaxf(v1.y, 0.f);
            }
            if (row < Nn)
                *(float2*)(C + (size_t)row * H + cc) = v0;
            if (row + 8 < Nn)
                *(float2*)(C + (size_t)(row + 8) * H + cc) = v1;
        }
    }
}

// ---------------- HMMA edge kernel (persistent, warp tiles, coalesced) -----
// Unchanged from R9 (bitwise-identical message path).
#define TW_STRIDE 8192
#define BH_OFF   32768
#define WES_OFF  41984
#define DST_OFF  42240
#define SMEM_EDGE 42752

__global__ void __launch_bounds__(128, 4)
edge_mma_kernel(const float* __restrict__ Ag, const int* __restrict__ src,
                const int* __restrict__ dstp, const float* __restrict__ ea,
                const int* __restrict__ perm, const float* __restrict__ weg,
                const __half* __restrict__ Bh_g,
                unsigned* __restrict__ aggr, int E, int nt32) {
    extern __shared__ char smc[];
    uint32_t sb = smem_u32(smc);
    int tid = threadIdx.x;
    int lane = tid & 31;
    int wid = tid >> 5;

    {
        const uint4* s4 = (const uint4*)Bh_g;
        uint4* d4 = (uint4*)(smc + BH_OFF);
        for (int i = tid; i < 576; i += 128) d4[i] = s4[i];
        if (tid < 64) ((float*)(smc + WES_OFF))[tid] = weg[tid];
    }
    __syncthreads();

    const float* wes = (const float*)(smc + WES_OFF);
    char* Tw = smc + wid * TW_STRIDE;
    uint32_t sbT = sb + wid * TW_STRIDE;
    float* Ds = (float*)Tw;
    int* dstw = (int*)(smc + DST_OFF + wid * 128);

    uint32_t aRow = (lane & 7) + 8u * ((lane >> 3) & 1);
    uint32_t aKoff = 16u * (lane >> 4);
    uint32_t bBase = 144u * (8u * ((lane >> 4) & 1) + (lane & 7)) +
                     16u * ((lane >> 3) & 1);

    int gc = lane & 15;
    int ghalf = lane >> 4;
    float4 wch = ((const float4*)wes)[gc];

    for (int t = blockIdx.x * 4 + wid; t < nt32; t += gridDim.x * 4) {
        {
            int slot = t * 32 + lane;
            int eidx = perm[min(slot, E - 1)];
            int s = src[eidx];
            float ev = ea[eidx];
            dstw[lane] = (slot < E) ? dstp[eidx] : -1;
#pragma unroll
            for (int rp = 0; rp < 16; rp++) {
                int r = rp * 2 + ghalf;
                int srow = __shfl_sync(0xFFFFFFFFu, s, r);
                float evr = __shfl_sync(0xFFFFFFFFu, ev, r);
                float4 a = ((const float4*)(Ag + (size_t)srow * H))[gc];
                float v0 = fmaxf(fmaf(evr, wch.x, a.x), 0.f);
                float v1 = fmaxf(fmaf(evr, wch.y, a.y), 0.f);
                float v2 = fmaxf(fmaf(evr, wch.z, a.z), 0.f);
                float v3 = fmaxf(fmaf(evr, wch.w, a.w), 0.f);
                uint2 hp;
                hp.x = cvt2h(v1, v0);
                hp.y = cvt2h(v3, v2);
                *(uint2*)(Tw + r * 144 + gc * 8) = hp;
            }
        }
        __syncwarp();

        float acc[2][8][4];
#pragma unroll
        for (int mt = 0; mt < 2; mt++)
#pragma unroll
            for (int nt = 0; nt < 8; nt++)
#pragma unroll
                for (int c = 0; c < 4; c++) acc[mt][nt][c] = 0.f;

#pragma unroll
        for (int ks = 0; ks < 4; ks++) {
            uint32_t ah0[4], ah1[4];
            ldsm4(ah0, sbT + 144u * aRow + 32u * ks + aKoff);
            ldsm4(ah1, sbT + 144u * (16 + aRow) + 32u * ks + aKoff);
#pragma unroll
            for (int ntp = 0; ntp < 4; ntp++) {
                uint32_t b4[4];
                ldsm4(b4, sb + BH_OFF + bBase + 2304u * ntp + 32u * ks);
                mma16816h(acc[0][2 * ntp], ah0, b4[0], b4[1]);
                mma16816h(acc[1][2 * ntp], ah1, b4[0], b4[1]);
                mma16816h(acc[0][2 * ntp + 1], ah0, b4[2], b4[3]);
                mma16816h(acc[1][2 * ntp + 1], ah1, b4[2], b4[3]);
            }
        }
        __syncwarp();

#pragma unroll
        for (int mt = 0; mt < 2; mt++) {
            int eb = mt * 16 + (lane >> 2);
            int h2i = lane & 1;
            int c4b = (lane & 3) >> 1;
#pragma unroll
            for (int nt = 0; nt < 8; nt++) {
                int c4 = nt * 2 + c4b;
                float2 v0 = make_float2(acc[mt][nt][0], acc[mt][nt][1]);
                float2 v1 = make_float2(acc[mt][nt][2], acc[mt][nt][3]);
                int e0 = eb, e1 = eb + 8;
                ((float2*)(Ds + (e0 * 16 + (c4 ^ (e0 & 15))) * 4))[h2i] = v0;
                ((float2*)(Ds + (e1 * 16 + (c4 ^ (e1 & 15))) * 4))[h2i] = v1;
            }
        }
        __syncwarp();

        {
            const float4* Ds4 = (const float4*)Ds;
            int ty = lane >> 3, tx = lane & 7;
            int cur = -2;
            float4 mA, mB;
#pragma unroll
            for (int r = 0; r < 8; r++) {
                int e = ty * 8 + r;
                int d = dstw[e];
                float4 a = Ds4[e * 16 + (tx ^ (e & 15))];
                float4 b = Ds4[e * 16 + ((8 + tx) ^ (e & 15))];
                if (r == 0 || d != cur) {
                    if (r > 0 && cur >= 0) {
                        unsigned* p0 = aggr + (size_t)cur * H + tx * 4;
                        atomicMin(p0 + 0, fenc(mA.x));
                        atomicMin(p0 + 1, fenc(mA.y));
                        atomicMin(p0 + 2, fenc(mA.z));
                        atomicMin(p0 + 3, fenc(mA.w));
                        unsigned* p1 = p0 + 32;
                        atomicMin(p1 + 0, fenc(mB.x));
                        atomicMin(p1 + 1, fenc(mB.y));
                        atomicMin(p1 + 2, fenc(mB.z));
                        atomicMin(p1 + 3, fenc(mB.w));
                    }
                    cur = d;
                    mA = a; mB = b;
                } else {
                    mA.x = fminf(mA.x, a.x); mA.y = fminf(mA.y, a.y);
                    mA.z = fminf(mA.z, a.z); mA.w = fminf(mA.w, a.w);
                    mB.x = fminf(mB.x, b.x); mB.y = fminf(mB.y, b.y);
                    mB.z = fminf(mB.z, b.z); mB.w = fminf(mB.w, b.w);
                }
            }
            if (cur >= 0) {
                unsigned* p0 = aggr + (size_t)cur * H + tx * 4;
                atomicMin(p0 + 0, fenc(mA.x));
                atomicMin(p0 + 1, fenc(mA.y));
                atomicMin(p0 + 2, fenc(mA.z));
                atomicMin(p0 + 3, fenc(mA.w));
                unsigned* p1 = p0 + 32;
                atomicMin(p1 + 0, fenc(mB.x));
                atomicMin(p1 + 1, fenc(mB.y));
                atomicMin(p1 + 2, fenc(mB.z));
                atomicMin(p1 + 3, fenc(mB.w));
            }
        }
        __syncwarp();
    }
}

// ---------------- host launch ----------------------------------------------
extern "C" void kernel_launch(void* const* d_in, const int* in_sizes, int n_in,
                              void* d_out, int out_size) {
    const float* x    = (const float*)d_in[0];
    const int*   ei   = (const int*)d_in[1];
    const float* ea   = (const float*)d_in[2];
    const float* embw = (const float*)d_in[3];
    const float* embb = (const float*)d_in[4];
    const float* mw1  = (const float*)d_in[5];
    const float* mb1  = (const float*)d_in[6];
    const float* mw2  = (const float*)d_in[7];
    const float* mb2  = (const float*)d_in[8];
    const float* uw1  = (const float*)d_in[9];
    const float* ub1  = (const float*)d_in[10];
    const float* uw2  = (const float*)d_in[11];
    const float* ub2  = (const float*)d_in[12];
    const float* fcw  = (const float*)d_in[13];
    const float* fcb  = (const float*)d_in[14];
    float* out = (float*)d_out;

    int N = in_sizes[0];
    int E = in_sizes[2];
    int L = in_sizes[6] / H;
    const int* src = ei;
    const int* dstp = ei + E;

    float* hbuf; float* Abuf; unsigned* aggr;
    int* cnt; int* cursor; int* perm;
    __half* Bh; __half* NBh; __half* NBl;
    cudaGetSymbolAddress((void**)&hbuf, g_h);
    cudaGetSymbolAddress((void**)&Abuf, g_A);
    cudaGetSymbolAddress((void**)&aggr, g_aggr);
    cudaGetSymbolAddress((void**)&cnt, g_cnt);
    cudaGetSymbolAddress((void**)&cursor, g_cursor);
    cudaGetSymbolAddress((void**)&perm, g_perm);
    cudaGetSymbolAddress((void**)&Bh, g_Bh);
    cudaGetSymbolAddress((void**)&NBh, g_NBh);
    cudaGetSymbolAddress((void**)&NBl, g_NBl);

    const int smN1 = NM_B_OFF + 1 * 18432 + 512;   // 55808
    const int smN2 = NM_B_OFF + 2 * 18432 + 512;   // 74240
    cudaFuncSetAttribute(edge_mma_kernel,
                         cudaFuncAttributeMaxDynamicSharedMemorySize, SMEM_EDGE);
    cudaFuncSetAttribute((node_mma<1, false, false>),
                         cudaFuncAttributeMaxDynamicSharedMemorySize, smN1);
    cudaFuncSetAttribute((node_mma<2, true, true>),
                         cudaFuncAttributeMaxDynamicSharedMemorySize, smN2);

    int nt32 = (E + 31) / 32;
    int edgeGrid = 148 * 4;
    if (edgeGrid > (nt32 + 3) / 4) edgeGrid = (nt32 + 3) / 4;
    int nodeBlocks = (N + 127) / 128;

    // embedding (+ zero cnt)
    embed_kernel<<<(N * H + 255) / 256, 256>>>(x, embw, embb, hbuf, cnt, N);
    // counting sort by dst (+ all fp16 weight prep, + aggr poison)
    count_kernel<<<(E + 255) / 256, 256>>>(dstp, cnt, E);
    scan_prep_kernel<<<1, 1024>>>(cnt, cursor, N, mw2, mw1, uw1, uw2, L);
    scatter_kernel<<<(E + 255) / 256, 256>>>(dstp, cursor, perm, aggr, E,
                                             N * H / 4);

    for (int l = 0; l < L; l++) {
        const float* w1 = mw1 + (size_t)l * (H + 1) * H;   // [65,64]
        // A = h @ W1[:64] + b1  (tensor pipe, 3-term fp16 split)
        node_mma<1, false, false><<<nodeBlocks, 128, smN1>>>(
            hbuf, nullptr, NBh + (size_t)(l * 4 + 0) * 4608,
            NBl + (size_t)(l * 4 + 0) * 4608, mb1 + (size_t)l * H,
            nullptr, nullptr, Abuf, N);
        // tensor-pipe edge message + scatter-min (coalesced gather)
        edge_mma_kernel<<<edgeGrid, 128, SMEM_EDGE>>>(
            Abuf, src, dstp, ea, perm, w1 + (size_t)H * H,
            Bh + (size_t)l * (64 * 72), aggr, E, nt32);
        // update MLP layer 1 (K=128, fused aggr decode + b2 + re-poison)
        node_mma<2, true, true><<<nodeBlocks, 128, smN2>>>(
            hbuf, aggr, NBh + (size_t)(l * 4 + 1) * 4608,
            NBl + (size_t)(l * 4 + 1) * 4608, ub1 + (size_t)l * H,
            mb2 + (size_t)l * H, aggr, Abuf, N);
        // update MLP layer 2
        node_mma<1, false, false><<<nodeBlocks, 128, smN1>>>(
            Abuf, nullptr, NBh + (size_t)(l * 4 + 3) * 4608,
            NBl + (size_t)(l * 4 + 3) * 4608, ub2 + (size_t)l * H,
            nullptr, nullptr, hbuf, N);
    }

    fc_kernel<<<(N + 255) / 256, 256>>>(hbuf, fcw, fcb, out, N);
}